// round 1
// baseline (speedup 1.0000x reference)
#include <cuda_runtime.h>
#include <cuda_bf16.h>
#include <math.h>

// ---------------------------------------------------------------------------
// ResidualRoPETransformer: B=2,U=32,A=512,E=256,NH=8,HD=32, T = 32768 tokens
// Round 0: fp32 baseline. Pipeline of 9 kernels, scratch in __device__ globals.
// ---------------------------------------------------------------------------

#define T_TOK 32768
#define EMB 256
#define NHEAD 8
#define HDIM 32
#define SEQ 512

// ---- scratch (static device globals; no runtime allocation) ----
__device__ float g_Wqkv[768 * 256];
__device__ float g_Wo[256 * 256];
__device__ float g_W1[256 * 256];
__device__ float g_W2[256 * 256];
__device__ float g_zln[(size_t)T_TOK * 256];
__device__ float g_qkv[(size_t)T_TOK * 768];
__device__ float g_q[(size_t)T_TOK * 256];
__device__ float g_k[(size_t)T_TOK * 256];
__device__ float g_v[(size_t)T_TOK * 256];
__device__ float g_att[(size_t)T_TOK * 256];
__device__ float g_h1[(size_t)T_TOK * 256];

// ---------------------------------------------------------------------------
__device__ __forceinline__ float blockReduceSum256(float v, float* red) {
    int lane = threadIdx.x & 31, w = threadIdx.x >> 5;
#pragma unroll
    for (int o = 16; o; o >>= 1) v += __shfl_xor_sync(0xffffffffu, v, o);
    __syncthreads();               // protect red[] from previous use
    if (lane == 0) red[w] = v;
    __syncthreads();
    float s = 0.f;
#pragma unroll
    for (int i = 0; i < 8; i++) s += red[i];
    return s;
}

// ---- weight norm: W[r][k] = g[r] * v[r][k] / ||v[r,:]||,  K=256 ----
__global__ void wnorm_kernel(const float* __restrict__ v, const float* __restrict__ g,
                             float* __restrict__ W) {
    __shared__ float red[8];
    size_t base = (size_t)blockIdx.x * 256;
    float x = v[base + threadIdx.x];
    float ss = blockReduceSum256(x * x, red);
    W[base + threadIdx.x] = x * g[blockIdx.x] * rsqrtf(ss);
}

// ---- layernorm over last dim 256, one block per token ----
__global__ void ln_kernel(const float* __restrict__ x, const float* __restrict__ g,
                          const float* __restrict__ b, float* __restrict__ y) {
    __shared__ float red[8];
    size_t base = (size_t)blockIdx.x * 256;
    float v = x[base + threadIdx.x];
    float mean = blockReduceSum256(v, red) * (1.f / 256.f);
    float d = v - mean;
    float var = blockReduceSum256(d * d, red) * (1.f / 256.f);
    y[base + threadIdx.x] = d * rsqrtf(var + 1e-5f) * g[threadIdx.x] + b[threadIdx.x];
}

// ---------------------------------------------------------------------------
// Tiled fp32 GEMM: C[M][N] = A[M][K] @ W[N][K]^T + bias[N]  (+ epilogue)
// BM=BN=128, BK=8, 256 threads, 8x8 microtile, register prefetch of next tile.
// mode: 0 plain, 1 gelu(exact), 2 add residual (res may alias C)
// ---------------------------------------------------------------------------
__global__ __launch_bounds__(256) void gemm_kernel(
    const float* __restrict__ A, const float* __restrict__ W,
    const float* __restrict__ bias, const float* __restrict__ res,
    float* __restrict__ C, int N, int K, int mode)
{
    __shared__ float As[8][128];
    __shared__ float Bs[8][128];
    int bm = blockIdx.y * 128;
    int bn = blockIdx.x * 128;
    int tid = threadIdx.x;
    int tx = (tid & 15) * 8;
    int ty = (tid >> 4) * 8;
    int lr = tid >> 1;
    int lk = (tid & 1) * 4;
    const float* Ap = A + (size_t)(bm + lr) * K + lk;
    const float* Wp = W + (size_t)(bn + lr) * K + lk;

    float acc[8][8];
#pragma unroll
    for (int i = 0; i < 8; i++)
#pragma unroll
        for (int j = 0; j < 8; j++) acc[i][j] = 0.f;

    float4 a = *(const float4*)(Ap);
    float4 wv = *(const float4*)(Wp);

    for (int k0 = 0; k0 < K; k0 += 8) {
        As[lk + 0][lr] = a.x; As[lk + 1][lr] = a.y; As[lk + 2][lr] = a.z; As[lk + 3][lr] = a.w;
        Bs[lk + 0][lr] = wv.x; Bs[lk + 1][lr] = wv.y; Bs[lk + 2][lr] = wv.z; Bs[lk + 3][lr] = wv.w;
        __syncthreads();

        float4 a_n = a, w_n = wv;
        if (k0 + 8 < K) {
            a_n = *(const float4*)(Ap + k0 + 8);
            w_n = *(const float4*)(Wp + k0 + 8);
        }

#pragma unroll
        for (int k = 0; k < 8; k++) {
            float4 a0 = *(const float4*)&As[k][ty];
            float4 a1 = *(const float4*)&As[k][ty + 4];
            float4 b0 = *(const float4*)&Bs[k][tx];
            float4 b1 = *(const float4*)&Bs[k][tx + 4];
            float ar[8] = {a0.x, a0.y, a0.z, a0.w, a1.x, a1.y, a1.z, a1.w};
            float br[8] = {b0.x, b0.y, b0.z, b0.w, b1.x, b1.y, b1.z, b1.w};
#pragma unroll
            for (int i = 0; i < 8; i++)
#pragma unroll
                for (int j = 0; j < 8; j++) acc[i][j] += ar[i] * br[j];
        }
        __syncthreads();
        a = a_n; wv = w_n;
    }

#pragma unroll
    for (int i = 0; i < 8; i++) {
        int m = bm + ty + i;
        size_t rowoff = (size_t)m * N + bn + tx;
#pragma unroll
        for (int j = 0; j < 8; j++) {
            float val = acc[i][j] + bias[bn + tx + j];
            if (mode == 1) {
                val = 0.5f * val * (1.f + erff(val * 0.7071067811865476f));
            } else if (mode == 2) {
                val += res[rowoff + j];
            }
            C[rowoff + j] = val;
        }
    }
}

// ---------------------------------------------------------------------------
// RoPE + scatter qkv[t][h*96 + {q:0-31,k:32-63,v:64-95}] into head-major
// layout [bu*8+h][a][d]. One thread per (t,h,pair).
// ---------------------------------------------------------------------------
__global__ void rope_kernel(const float* __restrict__ qkv,
                            float* __restrict__ q, float* __restrict__ k,
                            float* __restrict__ v) {
    int idx = blockIdx.x * blockDim.x + threadIdx.x;   // T * 8 * 16
    int i = idx & 15;
    int h = (idx >> 4) & 7;
    int t = idx >> 7;
    int a = t & 511;
    int bu = t >> 9;
    const float* src = qkv + (size_t)t * 768 + h * 96 + 2 * i;
    // freq = 10000^(-i/16) computed as exp2(-i * log2(10000)/16)
    float freq = exp2f(-(float)i * 0.8304820237218406f);
    float ang = (float)a * freq;
    float s, c;
    sincosf(ang, &s, &c);
    size_t dst = (((size_t)(bu * 8 + h) * 512) + a) * 32 + 2 * i;
    float x0 = src[0], x1 = src[1];
    q[dst] = x0 * c - x1 * s;  q[dst + 1] = x1 * c + x0 * s;
    x0 = src[32]; x1 = src[33];
    k[dst] = x0 * c - x1 * s;  k[dst + 1] = x1 * c + x0 * s;
    v[dst] = src[64];          v[dst + 1] = src[65];
}

// ---------------------------------------------------------------------------
// Attention: one block per (bu,h). K,V transposed into smem [32][516]
// (pad 516 -> conflict-free + float4-aligned). 8 warps x 64 rows,
// 2 query rows per pass (keeps score phase FMA-bound). P staged in smem.
// ---------------------------------------------------------------------------
#define VST 516
#define ATT_SMEM ((64 * VST + 16 * 512) * 4)

__global__ __launch_bounds__(256) void attn_kernel(
    const float* __restrict__ Q, const float* __restrict__ Kg,
    const float* __restrict__ Vg, float* __restrict__ O)
{
    extern __shared__ float sm[];
    float* Kt = sm;               // [32][516]
    float* Vt = sm + 32 * VST;    // [32][516]
    float* P  = sm + 64 * VST;    // [16][512]
    int bh = blockIdx.x;
    int tid = threadIdx.x;
    const float* kg = Kg + (size_t)bh * SEQ * HDIM;
    const float* vg = Vg + (size_t)bh * SEQ * HDIM;
    for (int idx = tid; idx < SEQ * HDIM; idx += 256) {
        int j = idx >> 5, d = idx & 31;
        Kt[d * VST + j] = kg[idx];
        Vt[d * VST + j] = vg[idx];
    }
    __syncthreads();

    int w = tid >> 5, lane = tid & 31;
    float* P0 = P + (w * 2) * 512;
    float* P1 = P0 + 512;
    int t_base = (bh >> 3) * 512;
    int col = (bh & 7) * 32 + lane;
    const float* vrow = Vt + lane * VST;
    const float sc = 0.17677669529663687f;   // 1/sqrt(32)

    for (int g = 0; g < 32; g++) {
        int a0 = w * 64 + g * 2;
        float q0 = Q[((size_t)bh * 512 + a0) * 32 + lane];
        float q1 = Q[((size_t)bh * 512 + a0 + 1) * 32 + lane];
        float acc0[16], acc1[16];
#pragma unroll
        for (int i = 0; i < 16; i++) { acc0[i] = 0.f; acc1[i] = 0.f; }

        // scores: lane owns keys j = c*128 + lane*4 + e
#pragma unroll
        for (int d = 0; d < 32; d++) {
            float qa = __shfl_sync(0xffffffffu, q0, d);
            float qb = __shfl_sync(0xffffffffu, q1, d);
            const float* kr = Kt + d * VST + lane * 4;
#pragma unroll
            for (int c = 0; c < 4; c++) {
                float4 kk = *(const float4*)(kr + c * 128);
                acc0[c*4+0] += qa * kk.x; acc0[c*4+1] += qa * kk.y;
                acc0[c*4+2] += qa * kk.z; acc0[c*4+3] += qa * kk.w;
                acc1[c*4+0] += qb * kk.x; acc1[c*4+1] += qb * kk.y;
                acc1[c*4+2] += qb * kk.z; acc1[c*4+3] += qb * kk.w;
            }
        }

        // softmax (two rows)
        float m0 = -1e30f, m1 = -1e30f;
#pragma unroll
        for (int i = 0; i < 16; i++) {
            acc0[i] *= sc; acc1[i] *= sc;
            m0 = fmaxf(m0, acc0[i]); m1 = fmaxf(m1, acc1[i]);
        }
#pragma unroll
        for (int o = 16; o; o >>= 1) {
            m0 = fmaxf(m0, __shfl_xor_sync(0xffffffffu, m0, o));
            m1 = fmaxf(m1, __shfl_xor_sync(0xffffffffu, m1, o));
        }
        float s0 = 0.f, s1 = 0.f;
#pragma unroll
        for (int i = 0; i < 16; i++) {
            acc0[i] = __expf(acc0[i] - m0); s0 += acc0[i];
            acc1[i] = __expf(acc1[i] - m1); s1 += acc1[i];
        }
#pragma unroll
        for (int o = 16; o; o >>= 1) {
            s0 += __shfl_xor_sync(0xffffffffu, s0, o);
            s1 += __shfl_xor_sync(0xffffffffu, s1, o);
        }
#pragma unroll
        for (int c = 0; c < 4; c++) {
            *(float4*)&P0[c * 128 + lane * 4] =
                make_float4(acc0[c*4], acc0[c*4+1], acc0[c*4+2], acc0[c*4+3]);
            *(float4*)&P1[c * 128 + lane * 4] =
                make_float4(acc1[c*4], acc1[c*4+1], acc1[c*4+2], acc1[c*4+3]);
        }
        __syncwarp();

        // out[d=lane] = sum_j P[j] * Vt[lane][j]
        float o0a = 0.f, o0b = 0.f, o1a = 0.f, o1b = 0.f;
#pragma unroll 4
        for (int j = 0; j < 512; j += 8) {
            float4 va = *(const float4*)(vrow + j);
            float4 vb = *(const float4*)(vrow + j + 4);
            float4 pa = *(const float4*)(P0 + j);
            float4 pb = *(const float4*)(P0 + j + 4);
            o0a += va.x * pa.x + va.y * pa.y + va.z * pa.z + va.w * pa.w;
            o0b += vb.x * pb.x + vb.y * pb.y + vb.z * pb.z + vb.w * pb.w;
            pa = *(const float4*)(P1 + j);
            pb = *(const float4*)(P1 + j + 4);
            o1a += va.x * pa.x + va.y * pa.y + va.z * pa.z + va.w * pa.w;
            o1b += vb.x * pb.x + vb.y * pb.y + vb.z * pb.z + vb.w * pb.w;
        }
        O[(size_t)(t_base + a0) * 256 + col]     = (o0a + o0b) / s0;
        O[(size_t)(t_base + a0 + 1) * 256 + col] = (o1a + o1b) / s1;
        __syncwarp();
    }
}

// ---------------------------------------------------------------------------
extern "C" void kernel_launch(void* const* d_in, const int* in_sizes, int n_in,
                              void* d_out, int out_size) {
    const float* z      = (const float*)d_in[0];
    const float* ln1_g  = (const float*)d_in[1];
    const float* ln1_b  = (const float*)d_in[2];
    const float* proj_v = (const float*)d_in[3];
    const float* proj_g = (const float*)d_in[4];
    const float* proj_b = (const float*)d_in[5];
    const float* ff_v   = (const float*)d_in[6];
    const float* ff_g   = (const float*)d_in[7];
    const float* ff_b   = (const float*)d_in[8];
    const float* ln2_g  = (const float*)d_in[9];
    const float* ln2_b  = (const float*)d_in[10];
    const float* w1_v   = (const float*)d_in[11];
    const float* w1_g   = (const float*)d_in[12];
    const float* w1_b   = (const float*)d_in[13];
    const float* w2_v   = (const float*)d_in[14];
    const float* w2_g   = (const float*)d_in[15];
    const float* w2_b   = (const float*)d_in[16];
    float* out = (float*)d_out;

    void *pWqkv, *pWo, *pW1, *pW2, *pzln, *pqkv, *pq, *pk, *pv, *patt, *ph1;
    cudaGetSymbolAddress(&pWqkv, g_Wqkv);
    cudaGetSymbolAddress(&pWo, g_Wo);
    cudaGetSymbolAddress(&pW1, g_W1);
    cudaGetSymbolAddress(&pW2, g_W2);
    cudaGetSymbolAddress(&pzln, g_zln);
    cudaGetSymbolAddress(&pqkv, g_qkv);
    cudaGetSymbolAddress(&pq, g_q);
    cudaGetSymbolAddress(&pk, g_k);
    cudaGetSymbolAddress(&pv, g_v);
    cudaGetSymbolAddress(&patt, g_att);
    cudaGetSymbolAddress(&ph1, g_h1);

    cudaFuncSetAttribute(attn_kernel, cudaFuncAttributeMaxDynamicSharedMemorySize, ATT_SMEM);

    // 1) weight norms
    wnorm_kernel<<<768, 256>>>(proj_v, proj_g, (float*)pWqkv);
    wnorm_kernel<<<256, 256>>>(ff_v, ff_g, (float*)pWo);
    wnorm_kernel<<<256, 256>>>(w1_v, w1_g, (float*)pW1);
    wnorm_kernel<<<256, 256>>>(w2_v, w2_g, (float*)pW2);

    // 2) LN1
    ln_kernel<<<T_TOK, 256>>>(z, ln1_g, ln1_b, (float*)pzln);

    // 3) QKV projection: [T,256] @ [768,256]^T
    gemm_kernel<<<dim3(6, 256), 256>>>((const float*)pzln, (const float*)pWqkv,
                                       proj_b, nullptr, (float*)pqkv, 768, 256, 0);

    // 4) RoPE + scatter to head-major
    rope_kernel<<<16384, 256>>>((const float*)pqkv, (float*)pq, (float*)pk, (float*)pv);

    // 5) attention
    attn_kernel<<<512, 256, ATT_SMEM>>>((const float*)pq, (const float*)pk,
                                        (const float*)pv, (float*)patt);

    // 6) Wo projection + residual add z  -> out
    gemm_kernel<<<dim3(2, 256), 256>>>((const float*)patt, (const float*)pWo,
                                       ff_b, z, out, 256, 256, 2);

    // 7) LN2
    ln_kernel<<<T_TOK, 256>>>(out, ln2_g, ln2_b, (float*)pzln);

    // 8) W1 + GELU
    gemm_kernel<<<dim3(2, 256), 256>>>((const float*)pzln, (const float*)pW1,
                                       w1_b, nullptr, (float*)ph1, 256, 256, 1);

    // 9) W2 + residual add (in place on out)
    gemm_kernel<<<dim3(2, 256), 256>>>((const float*)ph1, (const float*)pW2,
                                       w2_b, out, out, 256, 256, 2);
}

// round 5
// speedup vs baseline: 1.3583x; 1.3583x over previous
#include <cuda_runtime.h>
#include <cuda_bf16.h>
#include <math.h>
#include <stdint.h>

// ---------------------------------------------------------------------------
// ResidualRoPETransformer: B=2,U=32,A=512,E=256,NH=8,HD=32, T=32768 tokens
// Round 4: fix B-operand ldmatrix addressing (n-block/k-half swap) in HMMA GEMM.
// ---------------------------------------------------------------------------

#define T_TOK 32768
#define SEQ 512
#define HDIM 32

// ---- scratch (static device globals; no runtime allocation) ----
__device__ __nv_bfloat16 g_Wqkv[768 * 512];   // packed [hi(256)|lo(256)]
__device__ __nv_bfloat16 g_Wo[256 * 512];
__device__ __nv_bfloat16 g_W1[256 * 512];
__device__ __nv_bfloat16 g_W2[256 * 512];
__device__ __nv_bfloat16 g_zln[(size_t)T_TOK * 512];   // packed activations
__device__ __nv_bfloat16 g_att[(size_t)T_TOK * 512];
__device__ __nv_bfloat16 g_h1[(size_t)T_TOK * 512];
__device__ float g_qkv[(size_t)T_TOK * 768];
__device__ float g_q[(size_t)T_TOK * 256];
__device__ float g_k[(size_t)T_TOK * 256];
__device__ float g_v[(size_t)T_TOK * 256];

// ===========================================================================
// PTX helpers (sm_80-level only: cp.async, ldmatrix, mma.sync)
// ===========================================================================
__device__ __forceinline__ uint32_t smem_u32(const void* p) {
    uint32_t a;
    asm("{ .reg .u64 t; cvta.to.shared.u64 t, %1; cvt.u32.u64 %0, t; }"
        : "=r"(a) : "l"(p));
    return a;
}
#define CP_ASYNC16(dst, src) \
    asm volatile("cp.async.cg.shared.global [%0], [%1], 16;" :: "r"(dst), "l"(src))
#define CP_COMMIT() asm volatile("cp.async.commit_group;" ::: "memory")
#define CP_WAIT(n)  asm volatile("cp.async.wait_group %0;" :: "n"(n) : "memory")

#define LDSM_X4(r0, r1, r2, r3, addr) \
    asm volatile("ldmatrix.sync.aligned.m8n8.x4.shared.b16 {%0,%1,%2,%3},[%4];" \
                 : "=r"(r0), "=r"(r1), "=r"(r2), "=r"(r3) : "r"(addr))

#define MMA16816(d, a0, a1, a2, a3, b0, b1) \
    asm volatile("mma.sync.aligned.m16n8k16.row.col.f32.bf16.bf16.f32 " \
                 "{%0,%1,%2,%3},{%4,%5,%6,%7},{%8,%9},{%0,%1,%2,%3};" \
                 : "+f"((d)[0]), "+f"((d)[1]), "+f"((d)[2]), "+f"((d)[3]) \
                 : "r"(a0), "r"(a1), "r"(a2), "r"(a3), "r"(b0), "r"(b1))

__device__ __forceinline__ void split_bf16(float x, __nv_bfloat16& h, __nv_bfloat16& l) {
    h = __float2bfloat16(x);
    l = __float2bfloat16(x - __bfloat162float(h));
}

// ===========================================================================
__device__ __forceinline__ float blockReduceSum256(float v, float* red) {
    int lane = threadIdx.x & 31, w = threadIdx.x >> 5;
#pragma unroll
    for (int o = 16; o; o >>= 1) v += __shfl_xor_sync(0xffffffffu, v, o);
    __syncthreads();
    if (lane == 0) red[w] = v;
    __syncthreads();
    float s = 0.f;
#pragma unroll
    for (int i = 0; i < 8; i++) s += red[i];
    return s;
}

// ---- weight norm -> packed hi/lo bf16 [row][512] ----
__global__ void wnorm_kernel(const float* __restrict__ v, const float* __restrict__ g,
                             __nv_bfloat16* __restrict__ W) {
    __shared__ float red[8];
    size_t base = (size_t)blockIdx.x * 256;
    float x = v[base + threadIdx.x];
    float ss = blockReduceSum256(x * x, red);
    float w = x * g[blockIdx.x] * rsqrtf(ss);
    __nv_bfloat16 h, l;
    split_bf16(w, h, l);
    size_t ob = (size_t)blockIdx.x * 512 + threadIdx.x;
    W[ob] = h;
    W[ob + 256] = l;
}

// ---- layernorm -> packed hi/lo bf16 [token][512] ----
__global__ void ln_kernel(const float* __restrict__ x, const float* __restrict__ g,
                          const float* __restrict__ b, __nv_bfloat16* __restrict__ y) {
    __shared__ float red[8];
    size_t base = (size_t)blockIdx.x * 256;
    float v = x[base + threadIdx.x];
    float mean = blockReduceSum256(v, red) * (1.f / 256.f);
    float d = v - mean;
    float var = blockReduceSum256(d * d, red) * (1.f / 256.f);
    float o = d * rsqrtf(var + 1e-5f) * g[threadIdx.x] + b[threadIdx.x];
    __nv_bfloat16 h, l;
    split_bf16(o, h, l);
    size_t ob = (size_t)blockIdx.x * 512 + threadIdx.x;
    y[ob] = h;
    y[ob + 256] = l;
}

// ===========================================================================
// mma.sync bf16 GEMM: C[M][N] = A'[M][768] @ W'[N][768]^T  (split-3 packed K)
// BM=128 BN=128 BK=64, 256 thr, warp grid 2(M)x4(N), warp tile 64x32.
// Smem rows padded to 72 bf16 (144B) -> conflict-free ldmatrix phases.
// mode: 0 fp32+bias, 1 gelu->packed bf16, 2 bias+residual fp32
// ===========================================================================
#define ROWP 72
#define STG_BYTES (2 * 128 * ROWP * 2)   // A+B per stage = 36864
#define GEMM_SMEM (2 * STG_BYTES)

__global__ __launch_bounds__(256) void gemm_mma(
    const __nv_bfloat16* __restrict__ Ap, const __nv_bfloat16* __restrict__ Wp,
    const float* __restrict__ bias, const float* __restrict__ res,
    float* __restrict__ Cf, __nv_bfloat16* __restrict__ Cp, int N, int mode)
{
    extern __shared__ char dsm[];
    int tid = threadIdx.x, wid = tid >> 5, lane = tid & 31;
    int bm = blockIdx.y * 128, bn = blockIdx.x * 128;
    int wm = (wid & 1) * 64, wn = (wid >> 1) * 32;

    uint32_t sbase = smem_u32(dsm);
    int ldr = tid >> 3;          // 0..31: row group base for loads
    int ldc = (tid & 7) * 8;     // 0..56: bf16 col within row

    float acc[4][4][4];
#pragma unroll
    for (int mi = 0; mi < 4; mi++)
#pragma unroll
        for (int ni = 0; ni < 4; ni++)
#pragma unroll
            for (int e = 0; e < 4; e++) acc[mi][ni][e] = 0.f;

    // chunk -> (A k-offset, B k-offset) for split-3:
    // seg0: Ah*Bh, seg1: Ah*Bl, seg2: Al*Bh
    auto issue_loads = [&](int c) {
        int seg = c >> 2;
        int kg = (c & 3) * 64;
        int aoff = (seg == 2) ? 256 + kg : kg;
        int boff = (seg == 1) ? 256 + kg : kg;
        uint32_t st = sbase + (c & 1) * STG_BYTES;
#pragma unroll
        for (int i = 0; i < 4; i++) {
            int r = ldr + i * 32;
            CP_ASYNC16(st + r * 144 + ldc * 2,
                       Ap + (size_t)(bm + r) * 512 + aoff + ldc);
        }
        uint32_t stB = st + 128 * 144;
#pragma unroll
        for (int i = 0; i < 4; i++) {
            int r = ldr + i * 32;
            CP_ASYNC16(stB + r * 144 + ldc * 2,
                       Wp + (size_t)(bn + r) * 512 + boff + ldc);
        }
        CP_COMMIT();
    };

    issue_loads(0);

    for (int c = 0; c < 12; c++) {
        if (c + 1 < 12) { issue_loads(c + 1); CP_WAIT(1); } else { CP_WAIT(0); }
        __syncthreads();

        uint32_t stA = sbase + (c & 1) * STG_BYTES;
        uint32_t stB = stA + 128 * 144;
#pragma unroll
        for (int kk = 0; kk < 4; kk++) {
            uint32_t a[4][4], b[2][4];
#pragma unroll
            for (int mi = 0; mi < 4; mi++) {
                // matrices: (rows0-7,klo)(rows8-15,klo)(rows0-7,khi)(rows8-15,khi)
                uint32_t ad = stA + (wm + mi * 16 + (lane & 15)) * 144
                            + (kk * 16 + (lane >> 4) * 8) * 2;
                LDSM_X4(a[mi][0], a[mi][1], a[mi][2], a[mi][3], ad);
            }
#pragma unroll
            for (int nb = 0; nb < 2; nb++) {
                // required matrix order: (n0-7,klo)(n0-7,khi)(n8-15,klo)(n8-15,khi)
                // lanes 0-7 -> m0, 8-15 -> m1, 16-23 -> m2, 24-31 -> m3
                int nrow = wn + nb * 16 + ((lane >> 4) << 3) + (lane & 7);
                int koff = ((lane >> 3) & 1) * 8;
                uint32_t bd = stB + nrow * 144 + (kk * 16 + koff) * 2;
                LDSM_X4(b[nb][0], b[nb][1], b[nb][2], b[nb][3], bd);
            }
#pragma unroll
            for (int mi = 0; mi < 4; mi++) {
#pragma unroll
                for (int nb = 0; nb < 2; nb++) {
                    MMA16816(acc[mi][nb * 2 + 0], a[mi][0], a[mi][1], a[mi][2], a[mi][3],
                             b[nb][0], b[nb][1]);
                    MMA16816(acc[mi][nb * 2 + 1], a[mi][0], a[mi][1], a[mi][2], a[mi][3],
                             b[nb][2], b[nb][3]);
                }
            }
        }
        __syncthreads();
    }

    // ---- epilogue ----
    int cg = (lane & 3) * 2;          // col pair within n8
    int rg = lane >> 2;               // row within m8 pair
#pragma unroll
    for (int ni = 0; ni < 4; ni++) {
        int c0 = bn + wn + ni * 8 + cg;
        float2 b2 = *(const float2*)(bias + c0);
#pragma unroll
        for (int mi = 0; mi < 4; mi++) {
            int r0 = bm + wm + mi * 16 + rg;
#pragma unroll
            for (int h = 0; h < 2; h++) {
                int r = r0 + h * 8;
                float v0 = acc[mi][ni][h * 2 + 0] + b2.x;
                float v1 = acc[mi][ni][h * 2 + 1] + b2.y;
                if (mode == 1) {
                    v0 = 0.5f * v0 * (1.f + erff(v0 * 0.7071067811865476f));
                    v1 = 0.5f * v1 * (1.f + erff(v1 * 0.7071067811865476f));
                    union { __nv_bfloat16 b[2]; uint32_t u; } H, L;
                    split_bf16(v0, H.b[0], L.b[0]);
                    split_bf16(v1, H.b[1], L.b[1]);
                    *(uint32_t*)(Cp + (size_t)r * 512 + c0) = H.u;
                    *(uint32_t*)(Cp + (size_t)r * 512 + 256 + c0) = L.u;
                } else {
                    if (mode == 2) {
                        float2 rr = *(const float2*)(res + (size_t)r * N + c0);
                        v0 += rr.x; v1 += rr.y;
                    }
                    *(float2*)(Cf + (size_t)r * N + c0) = make_float2(v0, v1);
                }
            }
        }
    }
}

// ---------------------------------------------------------------------------
// RoPE + head-major scatter (reads fp32 qkv)
// ---------------------------------------------------------------------------
__global__ void rope_kernel(const float* __restrict__ qkv,
                            float* __restrict__ q, float* __restrict__ k,
                            float* __restrict__ v) {
    int idx = blockIdx.x * blockDim.x + threadIdx.x;
    int i = idx & 15;
    int h = (idx >> 4) & 7;
    int t = idx >> 7;
    int a = t & 511;
    int bu = t >> 9;
    const float* src = qkv + (size_t)t * 768 + h * 96 + 2 * i;
    float freq = exp2f(-(float)i * 0.8304820237218406f);
    float ang = (float)a * freq;
    float s, c;
    sincosf(ang, &s, &c);
    size_t dst = (((size_t)(bu * 8 + h) * 512) + a) * 32 + 2 * i;
    float x0 = src[0], x1 = src[1];
    q[dst] = x0 * c - x1 * s;  q[dst + 1] = x1 * c + x0 * s;
    x0 = src[32]; x1 = src[33];
    k[dst] = x0 * c - x1 * s;  k[dst + 1] = x1 * c + x0 * s;
    v[dst] = src[64];          v[dst + 1] = src[65];
}

// ---------------------------------------------------------------------------
// Attention (fp32), output written as packed hi/lo bf16
// ---------------------------------------------------------------------------
#define VST 516
#define ATT_SMEM ((64 * VST + 16 * 512) * 4)

__global__ __launch_bounds__(256) void attn_kernel(
    const float* __restrict__ Q, const float* __restrict__ Kg,
    const float* __restrict__ Vg, __nv_bfloat16* __restrict__ Op)
{
    extern __shared__ float sm[];
    float* Kt = sm;
    float* Vt = sm + 32 * VST;
    float* P  = sm + 64 * VST;
    int bh = blockIdx.x;
    int tid = threadIdx.x;
    const float* kg = Kg + (size_t)bh * SEQ * HDIM;
    const float* vg = Vg + (size_t)bh * SEQ * HDIM;
    for (int idx = tid; idx < SEQ * HDIM; idx += 256) {
        int j = idx >> 5, d = idx & 31;
        Kt[d * VST + j] = kg[idx];
        Vt[d * VST + j] = vg[idx];
    }
    __syncthreads();

    int w = tid >> 5, lane = tid & 31;
    float* P0 = P + (w * 2) * 512;
    float* P1 = P0 + 512;
    int t_base = (bh >> 3) * 512;
    int col = (bh & 7) * 32 + lane;
    const float* vrow = Vt + lane * VST;
    const float sc = 0.17677669529663687f;

    for (int g = 0; g < 32; g++) {
        int a0 = w * 64 + g * 2;
        float q0 = Q[((size_t)bh * 512 + a0) * 32 + lane];
        float q1 = Q[((size_t)bh * 512 + a0 + 1) * 32 + lane];
        float acc0[16], acc1[16];
#pragma unroll
        for (int i = 0; i < 16; i++) { acc0[i] = 0.f; acc1[i] = 0.f; }

#pragma unroll
        for (int d = 0; d < 32; d++) {
            float qa = __shfl_sync(0xffffffffu, q0, d);
            float qb = __shfl_sync(0xffffffffu, q1, d);
            const float* kr = Kt + d * VST + lane * 4;
#pragma unroll
            for (int c = 0; c < 4; c++) {
                float4 kk = *(const float4*)(kr + c * 128);
                acc0[c*4+0] += qa * kk.x; acc0[c*4+1] += qa * kk.y;
                acc0[c*4+2] += qa * kk.z; acc0[c*4+3] += qa * kk.w;
                acc1[c*4+0] += qb * kk.x; acc1[c*4+1] += qb * kk.y;
                acc1[c*4+2] += qb * kk.z; acc1[c*4+3] += qb * kk.w;
            }
        }

        float m0 = -1e30f, m1 = -1e30f;
#pragma unroll
        for (int i = 0; i < 16; i++) {
            acc0[i] *= sc; acc1[i] *= sc;
            m0 = fmaxf(m0, acc0[i]); m1 = fmaxf(m1, acc1[i]);
        }
#pragma unroll
        for (int o = 16; o; o >>= 1) {
            m0 = fmaxf(m0, __shfl_xor_sync(0xffffffffu, m0, o));
            m1 = fmaxf(m1, __shfl_xor_sync(0xffffffffu, m1, o));
        }
        float s0 = 0.f, s1 = 0.f;
#pragma unroll
        for (int i = 0; i < 16; i++) {
            acc0[i] = __expf(acc0[i] - m0); s0 += acc0[i];
            acc1[i] = __expf(acc1[i] - m1); s1 += acc1[i];
        }
#pragma unroll
        for (int o = 16; o; o >>= 1) {
            s0 += __shfl_xor_sync(0xffffffffu, s0, o);
            s1 += __shfl_xor_sync(0xffffffffu, s1, o);
        }
#pragma unroll
        for (int c = 0; c < 4; c++) {
            *(float4*)&P0[c * 128 + lane * 4] =
                make_float4(acc0[c*4], acc0[c*4+1], acc0[c*4+2], acc0[c*4+3]);
            *(float4*)&P1[c * 128 + lane * 4] =
                make_float4(acc1[c*4], acc1[c*4+1], acc1[c*4+2], acc1[c*4+3]);
        }
        __syncwarp();

        float o0a = 0.f, o0b = 0.f, o1a = 0.f, o1b = 0.f;
#pragma unroll 4
        for (int j = 0; j < 512; j += 8) {
            float4 va = *(const float4*)(vrow + j);
            float4 vb = *(const float4*)(vrow + j + 4);
            float4 pa = *(const float4*)(P0 + j);
            float4 pb = *(const float4*)(P0 + j + 4);
            o0a += va.x * pa.x + va.y * pa.y + va.z * pa.z + va.w * pa.w;
            o0b += vb.x * pb.x + vb.y * pb.y + vb.z * pb.z + vb.w * pb.w;
            pa = *(const float4*)(P1 + j);
            pb = *(const float4*)(P1 + j + 4);
            o1a += va.x * pa.x + va.y * pa.y + va.z * pa.z + va.w * pa.w;
            o1b += vb.x * pb.x + vb.y * pb.y + vb.z * pb.z + vb.w * pb.w;
        }
        float v0 = (o0a + o0b) / s0;
        float v1 = (o1a + o1b) / s1;
        __nv_bfloat16 h, l;
        split_bf16(v0, h, l);
        size_t ob0 = (size_t)(t_base + a0) * 512 + col;
        Op[ob0] = h; Op[ob0 + 256] = l;
        split_bf16(v1, h, l);
        size_t ob1 = (size_t)(t_base + a0 + 1) * 512 + col;
        Op[ob1] = h; Op[ob1 + 256] = l;
        __syncwarp();
    }
}

// ---------------------------------------------------------------------------
extern "C" void kernel_launch(void* const* d_in, const int* in_sizes, int n_in,
                              void* d_out, int out_size) {
    const float* z      = (const float*)d_in[0];
    const float* ln1_g  = (const float*)d_in[1];
    const float* ln1_b  = (const float*)d_in[2];
    const float* proj_v = (const float*)d_in[3];
    const float* proj_g = (const float*)d_in[4];
    const float* proj_b = (const float*)d_in[5];
    const float* ff_v   = (const float*)d_in[6];
    const float* ff_g   = (const float*)d_in[7];
    const float* ff_b   = (const float*)d_in[8];
    const float* ln2_g  = (const float*)d_in[9];
    const float* ln2_b  = (const float*)d_in[10];
    const float* w1_v   = (const float*)d_in[11];
    const float* w1_g   = (const float*)d_in[12];
    const float* w1_b   = (const float*)d_in[13];
    const float* w2_v   = (const float*)d_in[14];
    const float* w2_g   = (const float*)d_in[15];
    const float* w2_b   = (const float*)d_in[16];
    float* out = (float*)d_out;

    void *pWqkv, *pWo, *pW1, *pW2, *pzln, *pqkv, *pq, *pk, *pv, *patt, *ph1;
    cudaGetSymbolAddress(&pWqkv, g_Wqkv);
    cudaGetSymbolAddress(&pWo, g_Wo);
    cudaGetSymbolAddress(&pW1, g_W1);
    cudaGetSymbolAddress(&pW2, g_W2);
    cudaGetSymbolAddress(&pzln, g_zln);
    cudaGetSymbolAddress(&pqkv, g_qkv);
    cudaGetSymbolAddress(&pq, g_q);
    cudaGetSymbolAddress(&pk, g_k);
    cudaGetSymbolAddress(&pv, g_v);
    cudaGetSymbolAddress(&patt, g_att);
    cudaGetSymbolAddress(&ph1, g_h1);

    cudaFuncSetAttribute(attn_kernel, cudaFuncAttributeMaxDynamicSharedMemorySize, ATT_SMEM);
    cudaFuncSetAttribute(gemm_mma, cudaFuncAttributeMaxDynamicSharedMemorySize, GEMM_SMEM);

    // 1) weight norms -> packed bf16
    wnorm_kernel<<<768, 256>>>(proj_v, proj_g, (__nv_bfloat16*)pWqkv);
    wnorm_kernel<<<256, 256>>>(ff_v, ff_g, (__nv_bfloat16*)pWo);
    wnorm_kernel<<<256, 256>>>(w1_v, w1_g, (__nv_bfloat16*)pW1);
    wnorm_kernel<<<256, 256>>>(w2_v, w2_g, (__nv_bfloat16*)pW2);

    // 2) LN1 -> packed bf16
    ln_kernel<<<T_TOK, 256>>>(z, ln1_g, ln1_b, (__nv_bfloat16*)pzln);

    // 3) QKV projection
    gemm_mma<<<dim3(6, 256), 256, GEMM_SMEM>>>(
        (const __nv_bfloat16*)pzln, (const __nv_bfloat16*)pWqkv,
        proj_b, nullptr, (float*)pqkv, nullptr, 768, 0);

    // 4) RoPE + scatter
    rope_kernel<<<16384, 256>>>((const float*)pqkv, (float*)pq, (float*)pk, (float*)pv);

    // 5) attention -> packed bf16
    attn_kernel<<<512, 256, ATT_SMEM>>>((const float*)pq, (const float*)pk,
                                        (const float*)pv, (__nv_bfloat16*)patt);

    // 6) Wo + residual z -> out (fp32)
    gemm_mma<<<dim3(2, 256), 256, GEMM_SMEM>>>(
        (const __nv_bfloat16*)patt, (const __nv_bfloat16*)pWo,
        ff_b, z, out, nullptr, 256, 2);

    // 7) LN2 -> packed bf16
    ln_kernel<<<T_TOK, 256>>>(out, ln2_g, ln2_b, (__nv_bfloat16*)pzln);

    // 8) W1 + GELU -> packed bf16
    gemm_mma<<<dim3(2, 256), 256, GEMM_SMEM>>>(
        (const __nv_bfloat16*)pzln, (const __nv_bfloat16*)pW1,
        w1_b, nullptr, nullptr, (__nv_bfloat16*)ph1, 256, 1);

    // 9) W2 + residual -> out
    gemm_mma<<<dim3(2, 256), 256, GEMM_SMEM>>>(
        (const __nv_bfloat16*)ph1, (const __nv_bfloat16*)pW2,
        w2_b, out, out, nullptr, 256, 2);
}

// round 8
// speedup vs baseline: 3.0461x; 2.2426x over previous
#include <cuda_runtime.h>
#include <cuda_bf16.h>
#include <math.h>
#include <stdint.h>

// ---------------------------------------------------------------------------
// ResidualRoPETransformer: B=2,U=32,A=512,E=256,NH=8,HD=32, T=32768 tokens
// Round 6: flash-style HMMA attention (split-3 bf16) + split-emitting RoPE.
// GEMM pipeline unchanged from R5 (validated).
// ---------------------------------------------------------------------------

#define T_TOK 32768
#define SEQ 512
#define HDIM 32

// ---- scratch (static device globals; no runtime allocation) ----
__device__ __nv_bfloat16 g_Wqkv[768 * 512];   // packed [hi(256)|lo(256)]
__device__ __nv_bfloat16 g_Wo[256 * 512];
__device__ __nv_bfloat16 g_W1[256 * 512];
__device__ __nv_bfloat16 g_W2[256 * 512];
__device__ __nv_bfloat16 g_zln[(size_t)T_TOK * 512];   // packed activations
__device__ __nv_bfloat16 g_att[(size_t)T_TOK * 512];
__device__ __nv_bfloat16 g_h1[(size_t)T_TOK * 512];
__device__ float g_qkv[(size_t)T_TOK * 768];
__device__ __nv_bfloat16 g_qs[(size_t)512 * 512 * 64];  // [bh][a][qh32|ql32] (scaled)
__device__ __nv_bfloat16 g_ks[(size_t)512 * 512 * 64];  // [bh][a][kh32|kl32]
__device__ __nv_bfloat16 g_vt[(size_t)512 * 64 * 512];  // [bh][vh32|vl32][a]

// ===========================================================================
// PTX helpers (sm_80-level only: cp.async, ldmatrix, mma.sync)
// ===========================================================================
__device__ __forceinline__ uint32_t smem_u32(const void* p) {
    uint32_t a;
    asm("{ .reg .u64 t; cvta.to.shared.u64 t, %1; cvt.u32.u64 %0, t; }"
        : "=r"(a) : "l"(p));
    return a;
}
#define CP_ASYNC16(dst, src) \
    asm volatile("cp.async.cg.shared.global [%0], [%1], 16;" :: "r"(dst), "l"(src))
#define CP_COMMIT() asm volatile("cp.async.commit_group;" ::: "memory")
#define CP_WAIT(n)  asm volatile("cp.async.wait_group %0;" :: "n"(n) : "memory")

#define LDSM_X4(r0, r1, r2, r3, addr) \
    asm volatile("ldmatrix.sync.aligned.m8n8.x4.shared.b16 {%0,%1,%2,%3},[%4];" \
                 : "=r"(r0), "=r"(r1), "=r"(r2), "=r"(r3) : "r"(addr))

#define MMA16816(d, a0, a1, a2, a3, b0, b1) \
    asm volatile("mma.sync.aligned.m16n8k16.row.col.f32.bf16.bf16.f32 " \
                 "{%0,%1,%2,%3},{%4,%5,%6,%7},{%8,%9},{%0,%1,%2,%3};" \
                 : "+f"((d)[0]), "+f"((d)[1]), "+f"((d)[2]), "+f"((d)[3]) \
                 : "r"(a0), "r"(a1), "r"(a2), "r"(a3), "r"(b0), "r"(b1))

__device__ __forceinline__ void split_bf16(float x, __nv_bfloat16& h, __nv_bfloat16& l) {
    h = __float2bfloat16(x);
    l = __float2bfloat16(x - __bfloat162float(h));
}
__device__ __forceinline__ uint32_t packbf(float a, float b) {
    __nv_bfloat162 t = __floats2bfloat162_rn(a, b);   // .x = a (low), .y = b (high)
    return *(uint32_t*)&t;
}

// ===========================================================================
__device__ __forceinline__ float blockReduceSum256(float v, float* red) {
    int lane = threadIdx.x & 31, w = threadIdx.x >> 5;
#pragma unroll
    for (int o = 16; o; o >>= 1) v += __shfl_xor_sync(0xffffffffu, v, o);
    __syncthreads();
    if (lane == 0) red[w] = v;
    __syncthreads();
    float s = 0.f;
#pragma unroll
    for (int i = 0; i < 8; i++) s += red[i];
    return s;
}

// ---- weight norm -> packed hi/lo bf16 [row][512] ----
__global__ void wnorm_kernel(const float* __restrict__ v, const float* __restrict__ g,
                             __nv_bfloat16* __restrict__ W) {
    __shared__ float red[8];
    size_t base = (size_t)blockIdx.x * 256;
    float x = v[base + threadIdx.x];
    float ss = blockReduceSum256(x * x, red);
    float w = x * g[blockIdx.x] * rsqrtf(ss);
    __nv_bfloat16 h, l;
    split_bf16(w, h, l);
    size_t ob = (size_t)blockIdx.x * 512 + threadIdx.x;
    W[ob] = h;
    W[ob + 256] = l;
}

// ---- layernorm -> packed hi/lo bf16 [token][512] ----
__global__ void ln_kernel(const float* __restrict__ x, const float* __restrict__ g,
                          const float* __restrict__ b, __nv_bfloat16* __restrict__ y) {
    __shared__ float red[8];
    size_t base = (size_t)blockIdx.x * 256;
    float v = x[base + threadIdx.x];
    float mean = blockReduceSum256(v, red) * (1.f / 256.f);
    float d = v - mean;
    float var = blockReduceSum256(d * d, red) * (1.f / 256.f);
    float o = d * rsqrtf(var + 1e-5f) * g[threadIdx.x] + b[threadIdx.x];
    __nv_bfloat16 h, l;
    split_bf16(o, h, l);
    size_t ob = (size_t)blockIdx.x * 512 + threadIdx.x;
    y[ob] = h;
    y[ob + 256] = l;
}

// ===========================================================================
// mma.sync bf16 GEMM (unchanged from R5, validated)
// ===========================================================================
#define ROWP 72
#define STG_BYTES (2 * 128 * ROWP * 2)   // A+B per stage = 36864
#define GEMM_SMEM (2 * STG_BYTES)

__global__ __launch_bounds__(256) void gemm_mma(
    const __nv_bfloat16* __restrict__ Ap, const __nv_bfloat16* __restrict__ Wp,
    const float* __restrict__ bias, const float* __restrict__ res,
    float* __restrict__ Cf, __nv_bfloat16* __restrict__ Cp, int N, int mode)
{
    extern __shared__ char dsm[];
    int tid = threadIdx.x, wid = tid >> 5, lane = tid & 31;
    int bm = blockIdx.y * 128, bn = blockIdx.x * 128;
    int wm = (wid & 1) * 64, wn = (wid >> 1) * 32;

    uint32_t sbase = smem_u32(dsm);
    int ldr = tid >> 3;
    int ldc = (tid & 7) * 8;

    float acc[4][4][4];
#pragma unroll
    for (int mi = 0; mi < 4; mi++)
#pragma unroll
        for (int ni = 0; ni < 4; ni++)
#pragma unroll
            for (int e = 0; e < 4; e++) acc[mi][ni][e] = 0.f;

    auto issue_loads = [&](int c) {
        int seg = c >> 2;
        int kg = (c & 3) * 64;
        int aoff = (seg == 2) ? 256 + kg : kg;
        int boff = (seg == 1) ? 256 + kg : kg;
        uint32_t st = sbase + (c & 1) * STG_BYTES;
#pragma unroll
        for (int i = 0; i < 4; i++) {
            int r = ldr + i * 32;
            CP_ASYNC16(st + r * 144 + ldc * 2,
                       Ap + (size_t)(bm + r) * 512 + aoff + ldc);
        }
        uint32_t stB = st + 128 * 144;
#pragma unroll
        for (int i = 0; i < 4; i++) {
            int r = ldr + i * 32;
            CP_ASYNC16(stB + r * 144 + ldc * 2,
                       Wp + (size_t)(bn + r) * 512 + boff + ldc);
        }
        CP_COMMIT();
    };

    issue_loads(0);

    for (int c = 0; c < 12; c++) {
        if (c + 1 < 12) { issue_loads(c + 1); CP_WAIT(1); } else { CP_WAIT(0); }
        __syncthreads();

        uint32_t stA = sbase + (c & 1) * STG_BYTES;
        uint32_t stB = stA + 128 * 144;
#pragma unroll
        for (int kk = 0; kk < 4; kk++) {
            uint32_t a[4][4], b[2][4];
#pragma unroll
            for (int mi = 0; mi < 4; mi++) {
                uint32_t ad = stA + (wm + mi * 16 + (lane & 15)) * 144
                            + (kk * 16 + (lane >> 4) * 8) * 2;
                LDSM_X4(a[mi][0], a[mi][1], a[mi][2], a[mi][3], ad);
            }
#pragma unroll
            for (int nb = 0; nb < 2; nb++) {
                int nrow = wn + nb * 16 + ((lane >> 4) << 3) + (lane & 7);
                int koff = ((lane >> 3) & 1) * 8;
                uint32_t bd = stB + nrow * 144 + (kk * 16 + koff) * 2;
                LDSM_X4(b[nb][0], b[nb][1], b[nb][2], b[nb][3], bd);
            }
#pragma unroll
            for (int mi = 0; mi < 4; mi++) {
#pragma unroll
                for (int nb = 0; nb < 2; nb++) {
                    MMA16816(acc[mi][nb * 2 + 0], a[mi][0], a[mi][1], a[mi][2], a[mi][3],
                             b[nb][0], b[nb][1]);
                    MMA16816(acc[mi][nb * 2 + 1], a[mi][0], a[mi][1], a[mi][2], a[mi][3],
                             b[nb][2], b[nb][3]);
                }
            }
        }
        __syncthreads();
    }

    int cg = (lane & 3) * 2;
    int rg = lane >> 2;
#pragma unroll
    for (int ni = 0; ni < 4; ni++) {
        int c0 = bn + wn + ni * 8 + cg;
        float2 b2 = *(const float2*)(bias + c0);
#pragma unroll
        for (int mi = 0; mi < 4; mi++) {
            int r0 = bm + wm + mi * 16 + rg;
#pragma unroll
            for (int h = 0; h < 2; h++) {
                int r = r0 + h * 8;
                float v0 = acc[mi][ni][h * 2 + 0] + b2.x;
                float v1 = acc[mi][ni][h * 2 + 1] + b2.y;
                if (mode == 1) {
                    v0 = 0.5f * v0 * (1.f + erff(v0 * 0.7071067811865476f));
                    v1 = 0.5f * v1 * (1.f + erff(v1 * 0.7071067811865476f));
                    union { __nv_bfloat16 b[2]; uint32_t u; } H, L;
                    split_bf16(v0, H.b[0], L.b[0]);
                    split_bf16(v1, H.b[1], L.b[1]);
                    *(uint32_t*)(Cp + (size_t)r * 512 + c0) = H.u;
                    *(uint32_t*)(Cp + (size_t)r * 512 + 256 + c0) = L.u;
                } else {
                    if (mode == 2) {
                        float2 rr = *(const float2*)(res + (size_t)r * N + c0);
                        v0 += rr.x; v1 += rr.y;
                    }
                    *(float2*)(Cf + (size_t)r * N + c0) = make_float2(v0, v1);
                }
            }
        }
    }
}

// ---------------------------------------------------------------------------
// RoPE: stage qkv[t][h*96..h*96+96) in smem, emit split bf16:
//   Qs[bh][a][qh|ql] (scaled by 1/sqrt(32)), Ks[bh][a][kh|kl], Vt[bh][d(hi/lo)][a]
// block = (bh, atile of 128); 256 threads.
// ---------------------------------------------------------------------------
#define ROPE_SMEM (128 * 104 * 4)

__global__ __launch_bounds__(256) void rope2_kernel(
    const float* __restrict__ qkv,
    __nv_bfloat16* __restrict__ Qs, __nv_bfloat16* __restrict__ Ks,
    __nv_bfloat16* __restrict__ Vt)
{
    extern __shared__ float sq[];    // [128][104]
    int bh = blockIdx.x;
    int atile = blockIdx.y * 128;
    int h = bh & 7;
    int tbase = (bh >> 3) * 512 + atile;
    int tid = threadIdx.x, wid = tid >> 5, lane = tid & 31;

    for (int idx = tid; idx < 3072; idx += 256) {
        int r = idx / 24, c = idx % 24;
        CP_ASYNC16(smem_u32(sq + r * 104 + c * 4),
                   qkv + (size_t)(tbase + r) * 768 + h * 96 + c * 4);
    }
    CP_COMMIT(); CP_WAIT(0);
    __syncthreads();

    const float SCQ = 0.17677669529663687f;  // 1/sqrt(32)
    int i = lane & 15;
    bool lo_half = lane >= 16;
    float freq = exp2f(-(float)i * 0.8304820237218406f);

    for (int rr = wid; rr < 128; rr += 8) {
        int a = atile + rr;
        float s, c;
        sincosf((float)a * freq, &s, &c);
        const float* row = sq + rr * 104;
        float x0 = row[2 * i], x1 = row[2 * i + 1];
        float q0 = (x0 * c - x1 * s) * SCQ;
        float q1 = (x1 * c + x0 * s) * SCQ;
        x0 = row[32 + 2 * i]; x1 = row[33 + 2 * i];
        float k0 = x0 * c - x1 * s;
        float k1 = x1 * c + x0 * s;
        __nv_bfloat16 h0, l0, h1, l1;
        split_bf16(q0, h0, l0); split_bf16(q1, h1, l1);
        uint32_t qw = lo_half ? packbf(__bfloat162float(l0), __bfloat162float(l1))
                              : packbf(__bfloat162float(h0), __bfloat162float(h1));
        split_bf16(k0, h0, l0); split_bf16(k1, h1, l1);
        uint32_t kw = lo_half ? packbf(__bfloat162float(l0), __bfloat162float(l1))
                              : packbf(__bfloat162float(h0), __bfloat162float(h1));
        size_t rb = ((size_t)bh * 512 + a) * 64 + 2 * lane;
        *(uint32_t*)(Qs + rb) = qw;
        *(uint32_t*)(Ks + rb) = kw;
    }

    for (int dv = wid; dv < 64; dv += 8) {
        int d = dv & 31;
        bool vlo = dv >= 32;
#pragma unroll
        for (int j2 = 0; j2 < 4; j2++) {
            int ar = j2 * 32 + lane;
            float v = sq[ar * 104 + 64 + d];
            __nv_bfloat16 hh, ll;
            split_bf16(v, hh, ll);
            Vt[((size_t)bh * 64 + dv) * 512 + atile + ar] = vlo ? ll : hh;
        }
    }
}

// ---------------------------------------------------------------------------
// Flash-style HMMA attention. One CTA per bh. 8 warps x 64 rows.
// Q,K smem rows [a][64bf16] padded to 144B; Vt smem rows [d][512] padded 1040B.
// kv-tiles of 32; online softmax; split-3 on both QK^T and PV.
// Output: g_att packed hi/lo bf16 [t][512].
// ---------------------------------------------------------------------------
#define ATT2_SMEM (73728 + 73728 + 66560)

__global__ __launch_bounds__(256) void attn_mma(
    const __nv_bfloat16* __restrict__ Qs, const __nv_bfloat16* __restrict__ Ks,
    const __nv_bfloat16* __restrict__ Vt, __nv_bfloat16* __restrict__ Op)
{
    extern __shared__ char sm[];
    uint32_t sQ = smem_u32(sm);
    uint32_t sK = sQ + 73728;
    uint32_t sV = sQ + 147456;
    int bh = blockIdx.x, tid = threadIdx.x, wid = tid >> 5, lane = tid & 31;

    const __nv_bfloat16* qg = Qs + (size_t)bh * 512 * 64;
    const __nv_bfloat16* kg = Ks + (size_t)bh * 512 * 64;
    const __nv_bfloat16* vg = Vt + (size_t)bh * 64 * 512;
    for (int idx = tid; idx < 4096; idx += 256) {
        int r = idx >> 3, c = idx & 7;
        CP_ASYNC16(sQ + r * 144 + c * 16, qg + r * 64 + c * 8);
        CP_ASYNC16(sK + r * 144 + c * 16, kg + r * 64 + c * 8);
        int d = idx >> 6, cv = idx & 63;
        CP_ASYNC16(sV + d * 1040 + cv * 16, vg + d * 512 + cv * 8);
    }
    CP_COMMIT(); CP_WAIT(0);
    __syncthreads();

    int wm = wid * 64;
    float acc[4][4][4];            // [mi][jv][4]
    float mst[4][2], lst[4][2];
#pragma unroll
    for (int mi = 0; mi < 4; mi++) {
        mst[mi][0] = -1e30f; mst[mi][1] = -1e30f;
        lst[mi][0] = 0.f;    lst[mi][1] = 0.f;
#pragma unroll
        for (int jv = 0; jv < 4; jv++)
#pragma unroll
            for (int e = 0; e < 4; e++) acc[mi][jv][e] = 0.f;
    }

    int lg8 = ((lane >> 4) << 3) + (lane & 7);   // ldsm B row-within-16 pattern
    int lk8 = ((lane >> 3) & 1) * 16;            // ldsm B k-half byte offset

    for (int kt = 0; kt < 16; kt++) {
        int kvb = kt * 32;

        // K B-frags: bK[n8 j][k16 kq][2]   (kq 0,1 = kh; 2,3 = kl)
        uint32_t bK[4][4][2];
#pragma unroll
        for (int g16 = 0; g16 < 2; g16++)
#pragma unroll
            for (int kq = 0; kq < 4; kq++) {
                uint32_t ad = sK + (kvb + g16 * 16 + lg8) * 144 + kq * 32 + lk8;
                uint32_t r0, r1, r2, r3;
                LDSM_X4(r0, r1, r2, r3, ad);
                bK[g16 * 2][kq][0] = r0;     bK[g16 * 2][kq][1] = r1;
                bK[g16 * 2 + 1][kq][0] = r2; bK[g16 * 2 + 1][kq][1] = r3;
            }
        // V B-frags: bVh/bVl [n8 jv][kstep][2]
        uint32_t bVh[4][2][2], bVl[4][2][2];
#pragma unroll
        for (int g16 = 0; g16 < 2; g16++)
#pragma unroll
            for (int ks = 0; ks < 2; ks++) {
                uint32_t kb = kvb * 2 + ks * 32 + lk8;
                uint32_t ad = sV + (g16 * 16 + lg8) * 1040 + kb;
                uint32_t r0, r1, r2, r3;
                LDSM_X4(r0, r1, r2, r3, ad);
                bVh[g16 * 2][ks][0] = r0;     bVh[g16 * 2][ks][1] = r1;
                bVh[g16 * 2 + 1][ks][0] = r2; bVh[g16 * 2 + 1][ks][1] = r3;
                ad += 32 * 1040;
                LDSM_X4(r0, r1, r2, r3, ad);
                bVl[g16 * 2][ks][0] = r0;     bVl[g16 * 2][ks][1] = r1;
                bVl[g16 * 2 + 1][ks][0] = r2; bVl[g16 * 2 + 1][ks][1] = r3;
            }

#pragma unroll
        for (int mi = 0; mi < 4; mi++) {
            // Q A-frags for this m-tile: aQ[k16 kq][4]
            uint32_t aQ[4][4];
#pragma unroll
            for (int kq = 0; kq < 4; kq++) {
                uint32_t ad = sQ + (wm + mi * 16 + (lane & 15)) * 144
                            + kq * 32 + (lane >> 4) * 16;
                LDSM_X4(aQ[kq][0], aQ[kq][1], aQ[kq][2], aQ[kq][3], ad);
            }
            // scores S (split-3): s[n8 j][4]
            float s[4][4];
#pragma unroll
            for (int j = 0; j < 4; j++) {
#pragma unroll
                for (int e = 0; e < 4; e++) s[j][e] = 0.f;
                MMA16816(s[j], aQ[0][0], aQ[0][1], aQ[0][2], aQ[0][3], bK[j][0][0], bK[j][0][1]);
                MMA16816(s[j], aQ[1][0], aQ[1][1], aQ[1][2], aQ[1][3], bK[j][1][0], bK[j][1][1]);
                MMA16816(s[j], aQ[0][0], aQ[0][1], aQ[0][2], aQ[0][3], bK[j][2][0], bK[j][2][1]);
                MMA16816(s[j], aQ[1][0], aQ[1][1], aQ[1][2], aQ[1][3], bK[j][3][0], bK[j][3][1]);
                MMA16816(s[j], aQ[2][0], aQ[2][1], aQ[2][2], aQ[2][3], bK[j][0][0], bK[j][0][1]);
                MMA16816(s[j], aQ[3][0], aQ[3][1], aQ[3][2], aQ[3][3], bK[j][1][0], bK[j][1][1]);
            }
            // online softmax (rows r0 = lane>>2, r1 = r0+8)
            float mx0 = -1e30f, mx1 = -1e30f;
#pragma unroll
            for (int j = 0; j < 4; j++) {
                mx0 = fmaxf(mx0, fmaxf(s[j][0], s[j][1]));
                mx1 = fmaxf(mx1, fmaxf(s[j][2], s[j][3]));
            }
            mx0 = fmaxf(mx0, __shfl_xor_sync(0xffffffffu, mx0, 1));
            mx0 = fmaxf(mx0, __shfl_xor_sync(0xffffffffu, mx0, 2));
            mx1 = fmaxf(mx1, __shfl_xor_sync(0xffffffffu, mx1, 1));
            mx1 = fmaxf(mx1, __shfl_xor_sync(0xffffffffu, mx1, 2));
            float mn0 = fmaxf(mst[mi][0], mx0);
            float mn1 = fmaxf(mst[mi][1], mx1);
            float al0 = __expf(mst[mi][0] - mn0);
            float al1 = __expf(mst[mi][1] - mn1);
            mst[mi][0] = mn0; mst[mi][1] = mn1;
            float sm0 = 0.f, sm1 = 0.f;
#pragma unroll
            for (int j = 0; j < 4; j++) {
                s[j][0] = __expf(s[j][0] - mn0); sm0 += s[j][0];
                s[j][1] = __expf(s[j][1] - mn0); sm0 += s[j][1];
                s[j][2] = __expf(s[j][2] - mn1); sm1 += s[j][2];
                s[j][3] = __expf(s[j][3] - mn1); sm1 += s[j][3];
            }
            sm0 += __shfl_xor_sync(0xffffffffu, sm0, 1);
            sm0 += __shfl_xor_sync(0xffffffffu, sm0, 2);
            sm1 += __shfl_xor_sync(0xffffffffu, sm1, 1);
            sm1 += __shfl_xor_sync(0xffffffffu, sm1, 2);
            lst[mi][0] = lst[mi][0] * al0 + sm0;
            lst[mi][1] = lst[mi][1] * al1 + sm1;
#pragma unroll
            for (int jv = 0; jv < 4; jv++) {
                acc[mi][jv][0] *= al0; acc[mi][jv][1] *= al0;
                acc[mi][jv][2] *= al1; acc[mi][jv][3] *= al1;
            }
            // pack P hi/lo A-frags (C-frag layout == A-frag layout)
            uint32_t aPh[2][4], aPl[2][4];
#pragma unroll
            for (int ks = 0; ks < 2; ks++) {
                int j0 = 2 * ks, j1 = 2 * ks + 1;
                aPh[ks][0] = packbf(s[j0][0], s[j0][1]);
                aPh[ks][1] = packbf(s[j0][2], s[j0][3]);
                aPh[ks][2] = packbf(s[j1][0], s[j1][1]);
                aPh[ks][3] = packbf(s[j1][2], s[j1][3]);
                __nv_bfloat162 h0 = *(__nv_bfloat162*)&aPh[ks][0];
                __nv_bfloat162 h1 = *(__nv_bfloat162*)&aPh[ks][1];
                __nv_bfloat162 h2 = *(__nv_bfloat162*)&aPh[ks][2];
                __nv_bfloat162 h3 = *(__nv_bfloat162*)&aPh[ks][3];
                aPl[ks][0] = packbf(s[j0][0] - __bfloat162float(h0.x),
                                    s[j0][1] - __bfloat162float(h0.y));
                aPl[ks][1] = packbf(s[j0][2] - __bfloat162float(h1.x),
                                    s[j0][3] - __bfloat162float(h1.y));
                aPl[ks][2] = packbf(s[j1][0] - __bfloat162float(h2.x),
                                    s[j1][1] - __bfloat162float(h2.y));
                aPl[ks][3] = packbf(s[j1][2] - __bfloat162float(h3.x),
                                    s[j1][3] - __bfloat162float(h3.y));
            }
            // PV (split-3)
#pragma unroll
            for (int jv = 0; jv < 4; jv++) {
                MMA16816(acc[mi][jv], aPh[0][0], aPh[0][1], aPh[0][2], aPh[0][3],
                         bVh[jv][0][0], bVh[jv][0][1]);
                MMA16816(acc[mi][jv], aPh[1][0], aPh[1][1], aPh[1][2], aPh[1][3],
                         bVh[jv][1][0], bVh[jv][1][1]);
                MMA16816(acc[mi][jv], aPh[0][0], aPh[0][1], aPh[0][2], aPh[0][3],
                         bVl[jv][0][0], bVl[jv][0][1]);
                MMA16816(acc[mi][jv], aPh[1][0], aPh[1][1], aPh[1][2], aPh[1][3],
                         bVl[jv][1][0], bVl[jv][1][1]);
                MMA16816(acc[mi][jv], aPl[0][0], aPl[0][1], aPl[0][2], aPl[0][3],
                         bVh[jv][0][0], bVh[jv][0][1]);
                MMA16816(acc[mi][jv], aPl[1][0], aPl[1][1], aPl[1][2], aPl[1][3],
                         bVh[jv][1][0], bVh[jv][1][1]);
            }
        }
    }

    // epilogue: normalize by l, write packed hi/lo bf16 into g_att [t][512]
    int tb = (bh >> 3) * 512;
    int cb = (bh & 7) * 32;
#pragma unroll
    for (int mi = 0; mi < 4; mi++) {
        float i0 = 1.f / lst[mi][0];
        float i1 = 1.f / lst[mi][1];
        int r0 = wm + mi * 16 + (lane >> 2);
#pragma unroll
        for (int jv = 0; jv < 4; jv++) {
            int col = cb + jv * 8 + 2 * (lane & 3);
            float v0 = acc[mi][jv][0] * i0, v1 = acc[mi][jv][1] * i0;
            __nv_bfloat16 h0, l0, h1, l1;
            split_bf16(v0, h0, l0); split_bf16(v1, h1, l1);
            size_t ob = (size_t)(tb + r0) * 512 + col;
            *(uint32_t*)(Op + ob) = packbf(__bfloat162float(h0), __bfloat162float(h1));
            *(uint32_t*)(Op + ob + 256) = packbf(__bfloat162float(l0), __bfloat162float(l1));
            v0 = acc[mi][jv][2] * i1; v1 = acc[mi][jv][3] * i1;
            split_bf16(v0, h0, l0); split_bf16(v1, h1, l1);
            ob = (size_t)(tb + r0 + 8) * 512 + col;
            *(uint32_t*)(Op + ob) = packbf(__bfloat162float(h0), __bfloat162float(h1));
            *(uint32_t*)(Op + ob + 256) = packbf(__bfloat162float(l0), __bfloat162float(l1));
        }
    }
}

// ---------------------------------------------------------------------------
extern "C" void kernel_launch(void* const* d_in, const int* in_sizes, int n_in,
                              void* d_out, int out_size) {
    const float* z      = (const float*)d_in[0];
    const float* ln1_g  = (const float*)d_in[1];
    const float* ln1_b  = (const float*)d_in[2];
    const float* proj_v = (const float*)d_in[3];
    const float* proj_g = (const float*)d_in[4];
    const float* proj_b = (const float*)d_in[5];
    const float* ff_v   = (const float*)d_in[6];
    const float* ff_g   = (const float*)d_in[7];
    const float* ff_b   = (const float*)d_in[8];
    const float* ln2_g  = (const float*)d_in[9];
    const float* ln2_b  = (const float*)d_in[10];
    const float* w1_v   = (const float*)d_in[11];
    const float* w1_g   = (const float*)d_in[12];
    const float* w1_b   = (const float*)d_in[13];
    const float* w2_v   = (const float*)d_in[14];
    const float* w2_g   = (const float*)d_in[15];
    const float* w2_b   = (const float*)d_in[16];
    float* out = (float*)d_out;

    void *pWqkv, *pWo, *pW1, *pW2, *pzln, *pqkv, *pqs, *pks, *pvt, *patt, *ph1;
    cudaGetSymbolAddress(&pWqkv, g_Wqkv);
    cudaGetSymbolAddress(&pWo, g_Wo);
    cudaGetSymbolAddress(&pW1, g_W1);
    cudaGetSymbolAddress(&pW2, g_W2);
    cudaGetSymbolAddress(&pzln, g_zln);
    cudaGetSymbolAddress(&pqkv, g_qkv);
    cudaGetSymbolAddress(&pqs, g_qs);
    cudaGetSymbolAddress(&pks, g_ks);
    cudaGetSymbolAddress(&pvt, g_vt);
    cudaGetSymbolAddress(&patt, g_att);
    cudaGetSymbolAddress(&ph1, g_h1);

    cudaFuncSetAttribute(gemm_mma, cudaFuncAttributeMaxDynamicSharedMemorySize, GEMM_SMEM);
    cudaFuncSetAttribute(rope2_kernel, cudaFuncAttributeMaxDynamicSharedMemorySize, ROPE_SMEM);
    cudaFuncSetAttribute(attn_mma, cudaFuncAttributeMaxDynamicSharedMemorySize, ATT2_SMEM);

    // 1) weight norms -> packed bf16
    wnorm_kernel<<<768, 256>>>(proj_v, proj_g, (__nv_bfloat16*)pWqkv);
    wnorm_kernel<<<256, 256>>>(ff_v, ff_g, (__nv_bfloat16*)pWo);
    wnorm_kernel<<<256, 256>>>(w1_v, w1_g, (__nv_bfloat16*)pW1);
    wnorm_kernel<<<256, 256>>>(w2_v, w2_g, (__nv_bfloat16*)pW2);

    // 2) LN1 -> packed bf16
    ln_kernel<<<T_TOK, 256>>>(z, ln1_g, ln1_b, (__nv_bfloat16*)pzln);

    // 3) QKV projection
    gemm_mma<<<dim3(6, 256), 256, GEMM_SMEM>>>(
        (const __nv_bfloat16*)pzln, (const __nv_bfloat16*)pWqkv,
        proj_b, nullptr, (float*)pqkv, nullptr, 768, 0);

    // 4) RoPE -> split bf16 Q/K + transposed split V
    rope2_kernel<<<dim3(512, 4), 256, ROPE_SMEM>>>(
        (const float*)pqkv, (__nv_bfloat16*)pqs, (__nv_bfloat16*)pks,
        (__nv_bfloat16*)pvt);

    // 5) attention (flash HMMA) -> packed bf16
    attn_mma<<<512, 256, ATT2_SMEM>>>(
        (const __nv_bfloat16*)pqs, (const __nv_bfloat16*)pks,
        (const __nv_bfloat16*)pvt, (__nv_bfloat16*)patt);

    // 6) Wo + residual z -> out (fp32)
    gemm_mma<<<dim3(2, 256), 256, GEMM_SMEM>>>(
        (const __nv_bfloat16*)patt, (const __nv_bfloat16*)pWo,
        ff_b, z, out, nullptr, 256, 2);

    // 7) LN2 -> packed bf16
    ln_kernel<<<T_TOK, 256>>>(out, ln2_g, ln2_b, (__nv_bfloat16*)pzln);

    // 8) W1 + GELU -> packed bf16
    gemm_mma<<<dim3(2, 256), 256, GEMM_SMEM>>>(
        (const __nv_bfloat16*)pzln, (const __nv_bfloat16*)pW1,
        w1_b, nullptr, nullptr, (__nv_bfloat16*)ph1, 256, 1);

    // 9) W2 + residual -> out
    gemm_mma<<<dim3(2, 256), 256, GEMM_SMEM>>>(
        (const __nv_bfloat16*)ph1, (const __nv_bfloat16*)pW2,
        w2_b, out, out, nullptr, 256, 2);
}

// round 10
// speedup vs baseline: 3.0532x; 1.0023x over previous
#include <cuda_runtime.h>
#include <cuda_bf16.h>
#include <math.h>
#include <stdint.h>

// ---------------------------------------------------------------------------
// ResidualRoPETransformer: B=2,U=32,A=512,E=256,NH=8,HD=32, T=32768 tokens
// Round 9: RoPE fused into QKV GEMM epilogue; V via ldmatrix.trans; wnorm merged.
// ---------------------------------------------------------------------------

#define T_TOK 32768
#define SEQ 512
#define HDIM 32

// ---- scratch (static device globals; no runtime allocation) ----
__device__ __nv_bfloat16 g_Wqkv[768 * 512];   // packed [hi(256)|lo(256)]
__device__ __nv_bfloat16 g_Wo[256 * 512];
__device__ __nv_bfloat16 g_W1[256 * 512];
__device__ __nv_bfloat16 g_W2[256 * 512];
__device__ __nv_bfloat16 g_zln[(size_t)T_TOK * 512];   // packed activations
__device__ __nv_bfloat16 g_att[(size_t)T_TOK * 512];
__device__ __nv_bfloat16 g_h1[(size_t)T_TOK * 512];
__device__ __nv_bfloat16 g_qs[(size_t)512 * 512 * 64];  // [bh][a][qh32|ql32] (scaled)
__device__ __nv_bfloat16 g_ks[(size_t)512 * 512 * 64];  // [bh][a][kh32|kl32]
__device__ __nv_bfloat16 g_vs[(size_t)512 * 512 * 64];  // [bh][a][vh32|vl32]
__device__ float2 g_rtbl[512 * 16];                     // (cos, sin) per (a, i)

// ===========================================================================
// PTX helpers (sm_80-level only: cp.async, ldmatrix, mma.sync)
// ===========================================================================
__device__ __forceinline__ uint32_t smem_u32(const void* p) {
    uint32_t a;
    asm("{ .reg .u64 t; cvta.to.shared.u64 t, %1; cvt.u32.u64 %0, t; }"
        : "=r"(a) : "l"(p));
    return a;
}
#define CP_ASYNC16(dst, src) \
    asm volatile("cp.async.cg.shared.global [%0], [%1], 16;" :: "r"(dst), "l"(src))
#define CP_COMMIT() asm volatile("cp.async.commit_group;" ::: "memory")
#define CP_WAIT(n)  asm volatile("cp.async.wait_group %0;" :: "n"(n) : "memory")

#define LDSM_X4(r0, r1, r2, r3, addr) \
    asm volatile("ldmatrix.sync.aligned.m8n8.x4.shared.b16 {%0,%1,%2,%3},[%4];" \
                 : "=r"(r0), "=r"(r1), "=r"(r2), "=r"(r3) : "r"(addr))
#define LDSM_X4_T(r0, r1, r2, r3, addr) \
    asm volatile("ldmatrix.sync.aligned.m8n8.x4.trans.shared.b16 {%0,%1,%2,%3},[%4];" \
                 : "=r"(r0), "=r"(r1), "=r"(r2), "=r"(r3) : "r"(addr))

#define MMA16816(d, a0, a1, a2, a3, b0, b1) \
    asm volatile("mma.sync.aligned.m16n8k16.row.col.f32.bf16.bf16.f32 " \
                 "{%0,%1,%2,%3},{%4,%5,%6,%7},{%8,%9},{%0,%1,%2,%3};" \
                 : "+f"((d)[0]), "+f"((d)[1]), "+f"((d)[2]), "+f"((d)[3]) \
                 : "r"(a0), "r"(a1), "r"(a2), "r"(a3), "r"(b0), "r"(b1))

__device__ __forceinline__ void split_bf16(float x, __nv_bfloat16& h, __nv_bfloat16& l) {
    h = __float2bfloat16(x);
    l = __float2bfloat16(x - __bfloat162float(h));
}
__device__ __forceinline__ uint32_t packbf(float a, float b) {
    __nv_bfloat162 t = __floats2bfloat162_rn(a, b);
    return *(uint32_t*)&t;
}
// pack split of (v0,v1): returns hi word, lo word
__device__ __forceinline__ void pack_split(float v0, float v1, uint32_t& hw, uint32_t& lw) {
    __nv_bfloat16 h0, l0, h1, l1;
    split_bf16(v0, h0, l0); split_bf16(v1, h1, l1);
    hw = packbf(__bfloat162float(h0), __bfloat162float(h1));
    lw = packbf(__bfloat162float(l0), __bfloat162float(l1));
}

// ===========================================================================
__device__ __forceinline__ float blockReduceSum256(float v, float* red) {
    int lane = threadIdx.x & 31, w = threadIdx.x >> 5;
#pragma unroll
    for (int o = 16; o; o >>= 1) v += __shfl_xor_sync(0xffffffffu, v, o);
    __syncthreads();
    if (lane == 0) red[w] = v;
    __syncthreads();
    float s = 0.f;
#pragma unroll
    for (int i = 0; i < 8; i++) s += red[i];
    return s;
}

// ---- rope table ----
__global__ void rope_tbl_kernel(float2* tbl) {
    int idx = blockIdx.x * 256 + threadIdx.x;    // 8192
    int a = idx >> 4, i = idx & 15;
    float freq = exp2f(-(float)i * 0.8304820237218406f);
    float s, c;
    sincosf((float)a * freq, &s, &c);
    tbl[idx] = make_float2(c, s);
}

// ---- all weight norms in one launch (grid 1536) ----
__global__ void wnorm_all(const float* __restrict__ pv, const float* __restrict__ pg,
                          const float* __restrict__ fv, const float* __restrict__ fg,
                          const float* __restrict__ w1v, const float* __restrict__ w1g,
                          const float* __restrict__ w2v, const float* __restrict__ w2g,
                          __nv_bfloat16* __restrict__ Wqkv, __nv_bfloat16* __restrict__ Wo,
                          __nv_bfloat16* __restrict__ W1, __nv_bfloat16* __restrict__ W2) {
    __shared__ float red[8];
    int b = blockIdx.x;
    const float *v, *g; __nv_bfloat16* W; int row;
    if (b < 768)       { v = pv;  g = pg;  W = Wqkv; row = b; }
    else if (b < 1024) { v = fv;  g = fg;  W = Wo;   row = b - 768; }
    else if (b < 1280) { v = w1v; g = w1g; W = W1;   row = b - 1024; }
    else               { v = w2v; g = w2g; W = W2;   row = b - 1280; }
    size_t base = (size_t)row * 256;
    float x = v[base + threadIdx.x];
    float ss = blockReduceSum256(x * x, red);
    float w = x * g[row] * rsqrtf(ss);
    __nv_bfloat16 h, l;
    split_bf16(w, h, l);
    size_t ob = (size_t)row * 512 + threadIdx.x;
    W[ob] = h;
    W[ob + 256] = l;
}

// ---- layernorm -> packed hi/lo bf16 [token][512] ----
__global__ void ln_kernel(const float* __restrict__ x, const float* __restrict__ g,
                          const float* __restrict__ b, __nv_bfloat16* __restrict__ y) {
    __shared__ float red[8];
    size_t base = (size_t)blockIdx.x * 256;
    float v = x[base + threadIdx.x];
    float mean = blockReduceSum256(v, red) * (1.f / 256.f);
    float d = v - mean;
    float var = blockReduceSum256(d * d, red) * (1.f / 256.f);
    float o = d * rsqrtf(var + 1e-5f) * g[threadIdx.x] + b[threadIdx.x];
    __nv_bfloat16 h, l;
    split_bf16(o, h, l);
    size_t ob = (size_t)blockIdx.x * 512 + threadIdx.x;
    y[ob] = h;
    y[ob + 256] = l;
}

// ===========================================================================
// mma.sync bf16 GEMM (split-3 packed K'=768).
// mode: 1 gelu->packed bf16, 2 bias+residual fp32, 3 qkv: bias+rope -> split Q/K/V
// ===========================================================================
#define ROWP 72
#define STG_BYTES (2 * 128 * ROWP * 2)   // A+B per stage = 36864
#define GEMM_SMEM (2 * STG_BYTES)
#define SCQ 0.17677669529663687f

__global__ __launch_bounds__(256) void gemm_mma(
    const __nv_bfloat16* __restrict__ Ap, const __nv_bfloat16* __restrict__ Wp,
    const float* __restrict__ bias, const float* __restrict__ res,
    float* __restrict__ Cf, __nv_bfloat16* __restrict__ Cp,
    const float2* __restrict__ rtbl,
    __nv_bfloat16* __restrict__ Oq, __nv_bfloat16* __restrict__ Ok,
    __nv_bfloat16* __restrict__ Ov,
    int N, int mode)
{
    extern __shared__ char dsm[];
    int tid = threadIdx.x, wid = tid >> 5, lane = tid & 31;
    int bm = blockIdx.y * 128, bn = blockIdx.x * 128;
    int wm = (wid & 1) * 64, wn = (wid >> 1) * 32;

    uint32_t sbase = smem_u32(dsm);
    int ldr = tid >> 3;
    int ldc = (tid & 7) * 8;

    float acc[4][4][4];
#pragma unroll
    for (int mi = 0; mi < 4; mi++)
#pragma unroll
        for (int ni = 0; ni < 4; ni++)
#pragma unroll
            for (int e = 0; e < 4; e++) acc[mi][ni][e] = 0.f;

    auto issue_loads = [&](int c) {
        int seg = c >> 2;
        int kg = (c & 3) * 64;
        int aoff = (seg == 2) ? 256 + kg : kg;
        int boff = (seg == 1) ? 256 + kg : kg;
        uint32_t st = sbase + (c & 1) * STG_BYTES;
#pragma unroll
        for (int i = 0; i < 4; i++) {
            int r = ldr + i * 32;
            CP_ASYNC16(st + r * 144 + ldc * 2,
                       Ap + (size_t)(bm + r) * 512 + aoff + ldc);
        }
        uint32_t stB = st + 128 * 144;
#pragma unroll
        for (int i = 0; i < 4; i++) {
            int r = ldr + i * 32;
            CP_ASYNC16(stB + r * 144 + ldc * 2,
                       Wp + (size_t)(bn + r) * 512 + boff + ldc);
        }
        CP_COMMIT();
    };

    issue_loads(0);

    for (int c = 0; c < 12; c++) {
        if (c + 1 < 12) { issue_loads(c + 1); CP_WAIT(1); } else { CP_WAIT(0); }
        __syncthreads();

        uint32_t stA = sbase + (c & 1) * STG_BYTES;
        uint32_t stB = stA + 128 * 144;
#pragma unroll
        for (int kk = 0; kk < 4; kk++) {
            uint32_t a[4][4], b[2][4];
#pragma unroll
            for (int mi = 0; mi < 4; mi++) {
                uint32_t ad = stA + (wm + mi * 16 + (lane & 15)) * 144
                            + (kk * 16 + (lane >> 4) * 8) * 2;
                LDSM_X4(a[mi][0], a[mi][1], a[mi][2], a[mi][3], ad);
            }
#pragma unroll
            for (int nb = 0; nb < 2; nb++) {
                int nrow = wn + nb * 16 + ((lane >> 4) << 3) + (lane & 7);
                int koff = ((lane >> 3) & 1) * 8;
                uint32_t bd = stB + nrow * 144 + (kk * 16 + koff) * 2;
                LDSM_X4(b[nb][0], b[nb][1], b[nb][2], b[nb][3], bd);
            }
#pragma unroll
            for (int mi = 0; mi < 4; mi++) {
#pragma unroll
                for (int nb = 0; nb < 2; nb++) {
                    MMA16816(acc[mi][nb * 2 + 0], a[mi][0], a[mi][1], a[mi][2], a[mi][3],
                             b[nb][0], b[nb][1]);
                    MMA16816(acc[mi][nb * 2 + 1], a[mi][0], a[mi][1], a[mi][2], a[mi][3],
                             b[nb][2], b[nb][3]);
                }
            }
        }
        __syncthreads();
    }

    int cg = (lane & 3) * 2;
    int rg = lane >> 2;
#pragma unroll
    for (int ni = 0; ni < 4; ni++) {
        int c0 = bn + wn + ni * 8 + cg;
        float2 b2 = *(const float2*)(bias + c0);
#pragma unroll
        for (int mi = 0; mi < 4; mi++) {
            int r0 = bm + wm + mi * 16 + rg;
#pragma unroll
            for (int h = 0; h < 2; h++) {
                int r = r0 + h * 8;
                float v0 = acc[mi][ni][h * 2 + 0] + b2.x;
                float v1 = acc[mi][ni][h * 2 + 1] + b2.y;
                if (mode == 1) {
                    v0 = 0.5f * v0 * (1.f + erff(v0 * 0.7071067811865476f));
                    v1 = 0.5f * v1 * (1.f + erff(v1 * 0.7071067811865476f));
                    uint32_t hw, lw;
                    pack_split(v0, v1, hw, lw);
                    *(uint32_t*)(Cp + (size_t)r * 512 + c0) = hw;
                    *(uint32_t*)(Cp + (size_t)r * 512 + 256 + c0) = lw;
                } else if (mode == 2) {
                    float2 rr = *(const float2*)(res + (size_t)r * N + c0);
                    *(float2*)(Cf + (size_t)r * N + c0) =
                        make_float2(v0 + rr.x, v1 + rr.y);
                } else {
                    // mode 3: qkv epilogue with fused RoPE + split writes
                    int hh = c0 / 96;
                    int rem = c0 - hh * 96;
                    int type = rem >> 5;        // 0=q 1=k 2=v
                    int i2 = rem & 31;          // even dim index within head
                    int a = r & 511;
                    int bh = ((r >> 9) << 3) + hh;
                    size_t ob = ((size_t)bh * 512 + a) * 64 + i2;
                    uint32_t hw, lw;
                    if (type == 2) {
                        pack_split(v0, v1, hw, lw);
                        *(uint32_t*)(Ov + ob) = hw;
                        *(uint32_t*)(Ov + ob + 32) = lw;
                    } else {
                        float2 cs = rtbl[a * 16 + (i2 >> 1)];
                        float q0 = v0 * cs.x - v1 * cs.y;
                        float q1 = v1 * cs.x + v0 * cs.y;
                        if (type == 0) { q0 *= SCQ; q1 *= SCQ; }
                        pack_split(q0, q1, hw, lw);
                        __nv_bfloat16* O = (type == 0) ? Oq : Ok;
                        *(uint32_t*)(O + ob) = hw;
                        *(uint32_t*)(O + ob + 32) = lw;
                    }
                }
            }
        }
    }
}

// ---------------------------------------------------------------------------
// Flash-style HMMA attention. One CTA per bh. 8 warps x 64 query rows.
// Q,K,V all row-major [a][64bf16] in smem, rows padded to 144B.
// V^T B-fragments obtained via ldmatrix.trans.
// ---------------------------------------------------------------------------
#define ATT2_SMEM (3 * 73728)

__global__ __launch_bounds__(256) void attn_mma(
    const __nv_bfloat16* __restrict__ Qs, const __nv_bfloat16* __restrict__ Ks,
    const __nv_bfloat16* __restrict__ Vs, __nv_bfloat16* __restrict__ Op)
{
    extern __shared__ char sm[];
    uint32_t sQ = smem_u32(sm);
    uint32_t sK = sQ + 73728;
    uint32_t sV = sQ + 147456;
    int bh = blockIdx.x, tid = threadIdx.x, wid = tid >> 5, lane = tid & 31;

    const __nv_bfloat16* qg = Qs + (size_t)bh * 512 * 64;
    const __nv_bfloat16* kg = Ks + (size_t)bh * 512 * 64;
    const __nv_bfloat16* vg = Vs + (size_t)bh * 512 * 64;
    for (int idx = tid; idx < 4096; idx += 256) {
        int r = idx >> 3, c = idx & 7;
        CP_ASYNC16(sQ + r * 144 + c * 16, qg + r * 64 + c * 8);
        CP_ASYNC16(sK + r * 144 + c * 16, kg + r * 64 + c * 8);
        CP_ASYNC16(sV + r * 144 + c * 16, vg + r * 64 + c * 8);
    }
    CP_COMMIT(); CP_WAIT(0);
    __syncthreads();

    int wm = wid * 64;
    float acc[4][4][4];
    float mst[4][2], lst[4][2];
#pragma unroll
    for (int mi = 0; mi < 4; mi++) {
        mst[mi][0] = -1e30f; mst[mi][1] = -1e30f;
        lst[mi][0] = 0.f;    lst[mi][1] = 0.f;
#pragma unroll
        for (int jv = 0; jv < 4; jv++)
#pragma unroll
            for (int e = 0; e < 4; e++) acc[mi][jv][e] = 0.f;
    }

    int lg8 = ((lane >> 4) << 3) + (lane & 7);   // ldsm B row-within-16 pattern
    int lk8 = ((lane >> 3) & 1) * 16;            // ldsm B k-half byte offset
    int vrow = ((lane >> 3) & 1) * 8 + (lane & 7);  // trans-ldsm row pattern
    int vcb = (lane >> 4) * 16;                     // trans-ldsm col-byte

    for (int kt = 0; kt < 16; kt++) {
        int kvb = kt * 32;

        // K B-frags: bK[n8 j][k16 kq][2]   (kq 0,1 = kh; 2,3 = kl)
        uint32_t bK[4][4][2];
#pragma unroll
        for (int g16 = 0; g16 < 2; g16++)
#pragma unroll
            for (int kq = 0; kq < 4; kq++) {
                uint32_t ad = sK + (kvb + g16 * 16 + lg8) * 144 + kq * 32 + lk8;
                uint32_t r0, r1, r2, r3;
                LDSM_X4(r0, r1, r2, r3, ad);
                bK[g16 * 2][kq][0] = r0;     bK[g16 * 2][kq][1] = r1;
                bK[g16 * 2 + 1][kq][0] = r2; bK[g16 * 2 + 1][kq][1] = r3;
            }
        // V^T B-frags via trans ldmatrix: bVh/bVl [n8 jv(d)][kstep][2]
        uint32_t bVh[4][2][2], bVl[4][2][2];
#pragma unroll
        for (int ks = 0; ks < 2; ks++) {
            uint32_t ad = sV + (kvb + ks * 16 + vrow) * 144 + vcb;
            uint32_t r0, r1, r2, r3;
            LDSM_X4_T(r0, r1, r2, r3, ad);           // d0-15 hi
            bVh[0][ks][0] = r0; bVh[0][ks][1] = r1;
            bVh[1][ks][0] = r2; bVh[1][ks][1] = r3;
            LDSM_X4_T(r0, r1, r2, r3, ad + 32);      // d16-31 hi
            bVh[2][ks][0] = r0; bVh[2][ks][1] = r1;
            bVh[3][ks][0] = r2; bVh[3][ks][1] = r3;
            LDSM_X4_T(r0, r1, r2, r3, ad + 64);      // d0-15 lo
            bVl[0][ks][0] = r0; bVl[0][ks][1] = r1;
            bVl[1][ks][0] = r2; bVl[1][ks][1] = r3;
            LDSM_X4_T(r0, r1, r2, r3, ad + 96);      // d16-31 lo
            bVl[2][ks][0] = r0; bVl[2][ks][1] = r1;
            bVl[3][ks][0] = r2; bVl[3][ks][1] = r3;
        }

#pragma unroll
        for (int mi = 0; mi < 4; mi++) {
            uint32_t aQ[4][4];
#pragma unroll
            for (int kq = 0; kq < 4; kq++) {
                uint32_t ad = sQ + (wm + mi * 16 + (lane & 15)) * 144
                            + kq * 32 + (lane >> 4) * 16;
                LDSM_X4(aQ[kq][0], aQ[kq][1], aQ[kq][2], aQ[kq][3], ad);
            }
            float s[4][4];
#pragma unroll
            for (int j = 0; j < 4; j++) {
#pragma unroll
                for (int e = 0; e < 4; e++) s[j][e] = 0.f;
                MMA16816(s[j], aQ[0][0], aQ[0][1], aQ[0][2], aQ[0][3], bK[j][0][0], bK[j][0][1]);
                MMA16816(s[j], aQ[1][0], aQ[1][1], aQ[1][2], aQ[1][3], bK[j][1][0], bK[j][1][1]);
                MMA16816(s[j], aQ[0][0], aQ[0][1], aQ[0][2], aQ[0][3], bK[j][2][0], bK[j][2][1]);
                MMA16816(s[j], aQ[1][0], aQ[1][1], aQ[1][2], aQ[1][3], bK[j][3][0], bK[j][3][1]);
                MMA16816(s[j], aQ[2][0], aQ[2][1], aQ[2][2], aQ[2][3], bK[j][0][0], bK[j][0][1]);
                MMA16816(s[j], aQ[3][0], aQ[3][1], aQ[3][2], aQ[3][3], bK[j][1][0], bK[j][1][1]);
            }
            float mx0 = -1e30f, mx1 = -1e30f;
#pragma unroll
            for (int j = 0; j < 4; j++) {
                mx0 = fmaxf(mx0, fmaxf(s[j][0], s[j][1]));
                mx1 = fmaxf(mx1, fmaxf(s[j][2], s[j][3]));
            }
            mx0 = fmaxf(mx0, __shfl_xor_sync(0xffffffffu, mx0, 1));
            mx0 = fmaxf(mx0, __shfl_xor_sync(0xffffffffu, mx0, 2));
            mx1 = fmaxf(mx1, __shfl_xor_sync(0xffffffffu, mx1, 1));
            mx1 = fmaxf(mx1, __shfl_xor_sync(0xffffffffu, mx1, 2));
            float mn0 = fmaxf(mst[mi][0], mx0);
            float mn1 = fmaxf(mst[mi][1], mx1);
            float al0 = __expf(mst[mi][0] - mn0);
            float al1 = __expf(mst[mi][1] - mn1);
            mst[mi][0] = mn0; mst[mi][1] = mn1;
            float sm0 = 0.f, sm1 = 0.f;
#pragma unroll
            for (int j = 0; j < 4; j++) {
                s[j][0] = __expf(s[j][0] - mn0); sm0 += s[j][0];
                s[j][1] = __expf(s[j][1] - mn0); sm0 += s[j][1];
                s[j][2] = __expf(s[j][2] - mn1); sm1 += s[j][2];
                s[j][3] = __expf(s[j][3] - mn1); sm1 += s[j][3];
            }
            sm0 += __shfl_xor_sync(0xffffffffu, sm0, 1);
            sm0 += __shfl_xor_sync(0xffffffffu, sm0, 2);
            sm1 += __shfl_xor_sync(0xffffffffu, sm1, 1);
            sm1 += __shfl_xor_sync(0xffffffffu, sm1, 2);
            lst[mi][0] = lst[mi][0] * al0 + sm0;
            lst[mi][1] = lst[mi][1] * al1 + sm1;
#pragma unroll
            for (int jv = 0; jv < 4; jv++) {
                acc[mi][jv][0] *= al0; acc[mi][jv][1] *= al0;
                acc[mi][jv][2] *= al1; acc[mi][jv][3] *= al1;
            }
            uint32_t aPh[2][4], aPl[2][4];
#pragma unroll
            for (int ks = 0; ks < 2; ks++) {
                int j0 = 2 * ks, j1 = 2 * ks + 1;
                aPh[ks][0] = packbf(s[j0][0], s[j0][1]);
                aPh[ks][1] = packbf(s[j0][2], s[j0][3]);
                aPh[ks][2] = packbf(s[j1][0], s[j1][1]);
                aPh[ks][3] = packbf(s[j1][2], s[j1][3]);
                __nv_bfloat162 h0 = *(__nv_bfloat162*)&aPh[ks][0];
                __nv_bfloat162 h1 = *(__nv_bfloat162*)&aPh[ks][1];
                __nv_bfloat162 h2 = *(__nv_bfloat162*)&aPh[ks][2];
                __nv_bfloat162 h3 = *(__nv_bfloat162*)&aPh[ks][3];
                aPl[ks][0] = packbf(s[j0][0] - __bfloat162float(h0.x),
                                    s[j0][1] - __bfloat162float(h0.y));
                aPl[ks][1] = packbf(s[j0][2] - __bfloat162float(h1.x),
                                    s[j0][3] - __bfloat162float(h1.y));
                aPl[ks][2] = packbf(s[j1][0] - __bfloat162float(h2.x),
                                    s[j1][1] - __bfloat162float(h2.y));
                aPl[ks][3] = packbf(s[j1][2] - __bfloat162float(h3.x),
                                    s[j1][3] - __bfloat162float(h3.y));
            }
#pragma unroll
            for (int jv = 0; jv < 4; jv++) {
                MMA16816(acc[mi][jv], aPh[0][0], aPh[0][1], aPh[0][2], aPh[0][3],
                         bVh[jv][0][0], bVh[jv][0][1]);
                MMA16816(acc[mi][jv], aPh[1][0], aPh[1][1], aPh[1][2], aPh[1][3],
                         bVh[jv][1][0], bVh[jv][1][1]);
                MMA16816(acc[mi][jv], aPh[0][0], aPh[0][1], aPh[0][2], aPh[0][3],
                         bVl[jv][0][0], bVl[jv][0][1]);
                MMA16816(acc[mi][jv], aPh[1][0], aPh[1][1], aPh[1][2], aPh[1][3],
                         bVl[jv][1][0], bVl[jv][1][1]);
                MMA16816(acc[mi][jv], aPl[0][0], aPl[0][1], aPl[0][2], aPl[0][3],
                         bVh[jv][0][0], bVh[jv][0][1]);
                MMA16816(acc[mi][jv], aPl[1][0], aPl[1][1], aPl[1][2], aPl[1][3],
                         bVh[jv][1][0], bVh[jv][1][1]);
            }
        }
    }

    int tb = (bh >> 3) * 512;
    int cb = (bh & 7) * 32;
#pragma unroll
    for (int mi = 0; mi < 4; mi++) {
        float i0 = 1.f / lst[mi][0];
        float i1 = 1.f / lst[mi][1];
        int r0 = wm + mi * 16 + (lane >> 2);
#pragma unroll
        for (int jv = 0; jv < 4; jv++) {
            int col = cb + jv * 8 + 2 * (lane & 3);
            uint32_t hw, lw;
            pack_split(acc[mi][jv][0] * i0, acc[mi][jv][1] * i0, hw, lw);
            size_t ob = (size_t)(tb + r0) * 512 + col;
            *(uint32_t*)(Op + ob) = hw;
            *(uint32_t*)(Op + ob + 256) = lw;
            pack_split(acc[mi][jv][2] * i1, acc[mi][jv][3] * i1, hw, lw);
            ob = (size_t)(tb + r0 + 8) * 512 + col;
            *(uint32_t*)(Op + ob) = hw;
            *(uint32_t*)(Op + ob + 256) = lw;
        }
    }
}

// ---------------------------------------------------------------------------
extern "C" void kernel_launch(void* const* d_in, const int* in_sizes, int n_in,
                              void* d_out, int out_size) {
    const float* z      = (const float*)d_in[0];
    const float* ln1_g  = (const float*)d_in[1];
    const float* ln1_b  = (const float*)d_in[2];
    const float* proj_v = (const float*)d_in[3];
    const float* proj_g = (const float*)d_in[4];
    const float* proj_b = (const float*)d_in[5];
    const float* ff_v   = (const float*)d_in[6];
    const float* ff_g   = (const float*)d_in[7];
    const float* ff_b   = (const float*)d_in[8];
    const float* ln2_g  = (const float*)d_in[9];
    const float* ln2_b  = (const float*)d_in[10];
    const float* w1_v   = (const float*)d_in[11];
    const float* w1_g   = (const float*)d_in[12];
    const float* w1_b   = (const float*)d_in[13];
    const float* w2_v   = (const float*)d_in[14];
    const float* w2_g   = (const float*)d_in[15];
    const float* w2_b   = (const float*)d_in[16];
    float* out = (float*)d_out;

    void *pWqkv, *pWo, *pW1, *pW2, *pzln, *pqs, *pks, *pvs, *patt, *ph1, *ptbl;
    cudaGetSymbolAddress(&pWqkv, g_Wqkv);
    cudaGetSymbolAddress(&pWo, g_Wo);
    cudaGetSymbolAddress(&pW1, g_W1);
    cudaGetSymbolAddress(&pW2, g_W2);
    cudaGetSymbolAddress(&pzln, g_zln);
    cudaGetSymbolAddress(&pqs, g_qs);
    cudaGetSymbolAddress(&pks, g_ks);
    cudaGetSymbolAddress(&pvs, g_vs);
    cudaGetSymbolAddress(&patt, g_att);
    cudaGetSymbolAddress(&ph1, g_h1);
    cudaGetSymbolAddress(&ptbl, g_rtbl);

    cudaFuncSetAttribute(gemm_mma, cudaFuncAttributeMaxDynamicSharedMemorySize, GEMM_SMEM);
    cudaFuncSetAttribute(attn_mma, cudaFuncAttributeMaxDynamicSharedMemorySize, ATT2_SMEM);

    // 0) rope table
    rope_tbl_kernel<<<32, 256>>>((float2*)ptbl);

    // 1) all weight norms
    wnorm_all<<<1536, 256>>>(proj_v, proj_g, ff_v, ff_g, w1_v, w1_g, w2_v, w2_g,
                             (__nv_bfloat16*)pWqkv, (__nv_bfloat16*)pWo,
                             (__nv_bfloat16*)pW1, (__nv_bfloat16*)pW2);

    // 2) LN1 -> packed bf16
    ln_kernel<<<T_TOK, 256>>>(z, ln1_g, ln1_b, (__nv_bfloat16*)pzln);

    // 3) QKV projection with fused bias+RoPE+split scatter
    gemm_mma<<<dim3(6, 256), 256, GEMM_SMEM>>>(
        (const __nv_bfloat16*)pzln, (const __nv_bfloat16*)pWqkv,
        proj_b, nullptr, nullptr, nullptr,
        (const float2*)ptbl, (__nv_bfloat16*)pqs, (__nv_bfloat16*)pks,
        (__nv_bfloat16*)pvs, 768, 3);

    // 4) attention (flash HMMA) -> packed bf16
    attn_mma<<<512, 256, ATT2_SMEM>>>(
        (const __nv_bfloat16*)pqs, (const __nv_bfloat16*)pks,
        (const __nv_bfloat16*)pvs, (__nv_bfloat16*)patt);

    // 5) Wo + residual z -> out (fp32)
    gemm_mma<<<dim3(2, 256), 256, GEMM_SMEM>>>(
        (const __nv_bfloat16*)patt, (const __nv_bfloat16*)pWo,
        ff_b, z, out, nullptr, nullptr, nullptr, nullptr, nullptr, 256, 2);

    // 6) LN2 -> packed bf16
    ln_kernel<<<T_TOK, 256>>>(out, ln2_g, ln2_b, (__nv_bfloat16*)pzln);

    // 7) W1 + GELU -> packed bf16
    gemm_mma<<<dim3(2, 256), 256, GEMM_SMEM>>>(
        (const __nv_bfloat16*)pzln, (const __nv_bfloat16*)pW1,
        w1_b, nullptr, nullptr, (__nv_bfloat16*)ph1,
        nullptr, nullptr, nullptr, nullptr, 256, 1);

    // 8) W2 + residual -> out
    gemm_mma<<<dim3(2, 256), 256, GEMM_SMEM>>>(
        (const __nv_bfloat16*)ph1, (const __nv_bfloat16*)pW2,
        w2_b, out, out, nullptr, nullptr, nullptr, nullptr, nullptr, 256, 2);
}